// round 4
// baseline (speedup 1.0000x reference)
#include <cuda_runtime.h>
#include <cuda_bf16.h>

#define MAX_NODES 100000
#define MAX_EDGES 1600000
#define D 64
#define EPS 1e-9f

// Scratch (no allocations allowed -> device globals)
static __device__ int  g_count[MAX_NODES];    // per-node in-degree
static __device__ int  g_offset[MAX_NODES];   // CSR row start
static __device__ int  g_cursor[MAX_NODES];   // scatter cursors (init = offset)
static __device__ int2 g_edges[MAX_EDGES];    // (col, val-as-int) sorted by row

// ---------------------------------------------------------------------------
// Kernel 1: zero histogram counters
// ---------------------------------------------------------------------------
__global__ void zero_count_kernel(int n) {
    int i = blockIdx.x * blockDim.x + threadIdx.x;
    if (i < n) g_count[i] = 0;
}

// ---------------------------------------------------------------------------
// Kernel 2: histogram of edge_row
// ---------------------------------------------------------------------------
__global__ void hist_kernel(const int* __restrict__ edge_row, int E) {
    int e = blockIdx.x * blockDim.x + threadIdx.x;
    if (e < E) atomicAdd(&g_count[__ldg(edge_row + e)], 1);
}

// ---------------------------------------------------------------------------
// Kernel 3: one-block exclusive scan over g_count -> g_offset, g_cursor
// ---------------------------------------------------------------------------
__global__ __launch_bounds__(1024)
void scan_kernel(int nNodes) {
    __shared__ int warpSums[32];
    int tid = threadIdx.x;
    int chunk = (nNodes + 1023) >> 10;
    int start = tid * chunk;
    int end = start + chunk; if (end > nNodes) end = nNodes;

    int sum = 0;
    for (int i = start; i < end; ++i) sum += g_count[i];

    // block-wide exclusive scan of per-thread sums
    int lane = tid & 31, warp = tid >> 5;
    int v = sum;
    #pragma unroll
    for (int off = 1; off < 32; off <<= 1) {
        int t = __shfl_up_sync(0xffffffffu, v, off);
        if (lane >= off) v += t;
    }
    if (lane == 31) warpSums[warp] = v;
    __syncthreads();
    if (warp == 0) {
        int w = (lane < 32) ? warpSums[lane] : 0;
        #pragma unroll
        for (int off = 1; off < 32; off <<= 1) {
            int t = __shfl_up_sync(0xffffffffu, w, off);
            if (lane >= off) w += t;
        }
        warpSums[lane] = w;
    }
    __syncthreads();
    int base = v - sum;                       // exclusive within warp
    if (warp > 0) base += warpSums[warp - 1]; // add preceding warps

    int run = base;
    for (int i = start; i < end; ++i) {
        int c = g_count[i];
        g_offset[i] = run;
        g_cursor[i] = run;
        run += c;
    }
}

// ---------------------------------------------------------------------------
// Kernel 4: scatter edges into CSR order (1 position-claim atomic per edge)
// ---------------------------------------------------------------------------
__global__ void edge_scatter_kernel(const int* __restrict__ edge_row,
                                    const int* __restrict__ edge_col,
                                    const float* __restrict__ edge_val,
                                    int E) {
    int e = blockIdx.x * blockDim.x + threadIdx.x;
    if (e >= E) return;
    int r = __ldg(edge_row + e);
    int pos = atomicAdd(&g_cursor[r], 1);
    g_edges[pos] = make_int2(__ldg(edge_col + e),
                             __float_as_int(__ldg(edge_val + e)));
}

// ---------------------------------------------------------------------------
// Fused hop transform: GEMM(64x64) + bias + ReLU + row-norm, warp-collective.
// Lane owns output features j=lane, j=lane+32. Input row lives in xv (float2
// per lane, features 2*lane, 2*lane+1). sW is transposed + pair-interleaved:
// sW[k*64 + 2*j' + p], j = j' + 32*p -> one conflict-free LDS.64 per k.
// ---------------------------------------------------------------------------
__device__ __forceinline__ float2 hop_transform(float2 xv,
                                                const float* __restrict__ sW,
                                                float b_a, float b_b,
                                                float sc_a, float sc_b,
                                                float of_a, float of_b,
                                                int lane) {
    float acc_a = 0.f, acc_b = 0.f;
    const float2* sW2 = reinterpret_cast<const float2*>(sW);
    #pragma unroll
    for (int k2 = 0; k2 < 32; ++k2) {
        float xa = __shfl_sync(0xffffffffu, xv.x, k2);
        float xb = __shfl_sync(0xffffffffu, xv.y, k2);
        float2 w0 = sW2[(2 * k2 + 0) * 32 + lane];
        float2 w1 = sW2[(2 * k2 + 1) * 32 + lane];
        acc_a = fmaf(xa, w0.x, acc_a);
        acc_a = fmaf(xb, w1.x, acc_a);
        acc_b = fmaf(xa, w0.y, acc_b);
        acc_b = fmaf(xb, w1.y, acc_b);
    }
    float ha = fmaxf(acc_a + b_a, 0.f);
    float hb = fmaxf(acc_b + b_b, 0.f);
    float s = ha + hb;
    float q = ha * ha + hb * hb;
    #pragma unroll
    for (int off = 16; off; off >>= 1) {
        s += __shfl_xor_sync(0xffffffffu, s, off);
        q += __shfl_xor_sync(0xffffffffu, q, off);
    }
    float mean = s * (1.0f / 64.0f);
    float var  = q * (1.0f / 64.0f) - mean * mean + EPS;
    float rinv = rsqrtf(var);
    float ra = (ha - mean) * sc_a * rinv + of_a;
    float rb = (hb - mean) * sc_b * rinv + of_b;
    return make_float2(ra, rb);
}

// ---------------------------------------------------------------------------
// Kernel 5: fused gather-SpMM + dual hop transform + sum. Warp per node.
// ---------------------------------------------------------------------------
__global__ __launch_bounds__(256)
void fused_kernel(const float* __restrict__ x,
                  const float* __restrict__ W0, const float* __restrict__ b0,
                  const float* __restrict__ s0, const float* __restrict__ o0,
                  const float* __restrict__ W1, const float* __restrict__ b1,
                  const float* __restrict__ s1, const float* __restrict__ o1,
                  float* __restrict__ out, int nNodes) {
    __shared__ float sW0[D * D];
    __shared__ float sW1[D * D];
    __shared__ float sPar[6 * D];

    for (int idx = threadIdx.x; idx < D * D; idx += 256) {
        int j = idx >> 6;
        int k = idx & 63;
        int dst = k * 64 + ((j & 31) << 1) + (j >> 5);
        sW0[dst] = W0[idx];
        sW1[dst] = W1[idx];
    }
    for (int idx = threadIdx.x; idx < 6 * D; idx += 256) {
        int which = idx >> 6, t = idx & 63;
        const float* src = (which == 0) ? b0 : (which == 1) ? s0 : (which == 2) ? o0
                         : (which == 3) ? b1 : (which == 4) ? s1 : o1;
        sPar[idx] = src[t];
    }
    __syncthreads();

    int lane = threadIdx.x & 31;
    int warp = threadIdx.x >> 5;
    int node = blockIdx.x * 8 + warp;
    if (node >= nNodes) return;

    const float2* x2 = reinterpret_cast<const float2*>(x);

    // ---- gather-side SpMM: agg = sum_e val[e] * x[col[e]] (2 feats/lane) ----
    int start = g_offset[node];
    int cnt   = g_count[node];
    float2 agg = make_float2(0.f, 0.f);
    for (int base = 0; base < cnt; base += 32) {
        int idx = base + lane;
        int2 ev = (idx < cnt) ? g_edges[start + idx] : make_int2(0, 0);
        int m = cnt - base; if (m > 32) m = 32;
        for (int t = 0; t < m; ++t) {
            int   col = __shfl_sync(0xffffffffu, ev.x, t);
            float v   = __int_as_float(__shfl_sync(0xffffffffu, ev.y, t));
            float2 xr = x2[col * 32 + lane];
            agg.x = fmaf(v, xr.x, agg.x);
            agg.y = fmaf(v, xr.y, agg.y);
        }
    }

    const float* pb0 = sPar;       const float* ps0 = sPar + 64;  const float* po0 = sPar + 128;
    const float* pb1 = sPar + 192; const float* ps1 = sPar + 256; const float* po1 = sPar + 320;

    float2 xrow = x2[node * 32 + lane];
    float2 r0 = hop_transform(xrow, sW0,
                              pb0[lane], pb0[lane + 32],
                              ps0[lane], ps0[lane + 32],
                              po0[lane], po0[lane + 32], lane);
    float2 r1 = hop_transform(agg, sW1,
                              pb1[lane], pb1[lane + 32],
                              ps1[lane], ps1[lane + 32],
                              po1[lane], po1[lane + 32], lane);

    out[(size_t)node * D + lane]      = r0.x + r1.x;
    out[(size_t)node * D + lane + 32] = r0.y + r1.y;
}

// ---------------------------------------------------------------------------
// Launch
// ---------------------------------------------------------------------------
extern "C" void kernel_launch(void* const* d_in, const int* in_sizes, int n_in,
                              void* d_out, int out_size) {
    const float* x        = (const float*)d_in[0];
    const float* edge_val = (const float*)d_in[1];
    const float* W0       = (const float*)d_in[2];
    const float* b0       = (const float*)d_in[3];
    const float* scale0   = (const float*)d_in[4];
    const float* offset0  = (const float*)d_in[5];
    const float* W1       = (const float*)d_in[6];
    const float* b1       = (const float*)d_in[7];
    const float* scale1   = (const float*)d_in[8];
    const float* offset1  = (const float*)d_in[9];
    const int*   edge_row = (const int*)d_in[10];
    const int*   edge_col = (const int*)d_in[11];
    float* out = (float*)d_out;

    int nNodes = in_sizes[0] / D;
    int E = in_sizes[1];

    zero_count_kernel<<<(nNodes + 255) / 256, 256>>>(nNodes);
    hist_kernel<<<(E + 255) / 256, 256>>>(edge_row, E);
    scan_kernel<<<1, 1024>>>(nNodes);
    edge_scatter_kernel<<<(E + 255) / 256, 256>>>(edge_row, edge_col, edge_val, E);

    int grid_c = (nNodes + 7) / 8;
    fused_kernel<<<grid_c, 256>>>(x, W0, b0, scale0, offset0,
                                  W1, b1, scale1, offset1, out, nNodes);
}

// round 6
// speedup vs baseline: 1.0806x; 1.0806x over previous
#include <cuda_runtime.h>
#include <cuda_bf16.h>

#define MAX_NODES 100000
#define MAX_EDGES 1600000
#define D 64
#define EPS 1e-9f

// Scratch (no allocations allowed -> device globals)
static __device__ int  g_count[MAX_NODES];    // per-node in-degree
static __device__ int  g_offset[MAX_NODES];   // CSR row start
static __device__ int  g_cursor[MAX_NODES];   // scatter cursors (init = offset)
static __device__ int2 g_edges[MAX_EDGES];    // (col, val-as-int) sorted by row

// ---------------------------------------------------------------------------
// Kernel 1: zero histogram counters
// ---------------------------------------------------------------------------
__global__ void zero_count_kernel(int n) {
    int i = blockIdx.x * blockDim.x + threadIdx.x;
    if (i < n) g_count[i] = 0;
}

// ---------------------------------------------------------------------------
// Kernel 2: histogram of edge_row
// ---------------------------------------------------------------------------
__global__ void hist_kernel(const int* __restrict__ edge_row, int E) {
    int e = blockIdx.x * blockDim.x + threadIdx.x;
    if (e < E) atomicAdd(&g_count[__ldg(edge_row + e)], 1);
}

// ---------------------------------------------------------------------------
// Kernel 3: one-block exclusive scan over g_count -> g_offset, g_cursor
// ---------------------------------------------------------------------------
__global__ __launch_bounds__(1024)
void scan_kernel(int nNodes) {
    __shared__ int warpSums[32];
    int tid = threadIdx.x;
    const int chunk = 100;
    int start = tid * chunk;
    int end = start + chunk; if (end > nNodes) end = nNodes;

    int sum = 0;
    if (start < nNodes) {
        const int4* c4 = reinterpret_cast<const int4*>(g_count + start);
        int nfull = (end - start) >> 2;
        for (int i = 0; i < nfull; ++i) {
            int4 v = c4[i];
            sum += v.x + v.y + v.z + v.w;
        }
        for (int i = start + (nfull << 2); i < end; ++i) sum += g_count[i];
    }

    int lane = tid & 31, warp = tid >> 5;
    int v = sum;
    #pragma unroll
    for (int off = 1; off < 32; off <<= 1) {
        int t = __shfl_up_sync(0xffffffffu, v, off);
        if (lane >= off) v += t;
    }
    if (lane == 31) warpSums[warp] = v;
    __syncthreads();
    if (warp == 0) {
        int w = warpSums[lane];
        #pragma unroll
        for (int off = 1; off < 32; off <<= 1) {
            int t = __shfl_up_sync(0xffffffffu, w, off);
            if (lane >= off) w += t;
        }
        warpSums[lane] = w;
    }
    __syncthreads();
    int base = v - sum;
    if (warp > 0) base += warpSums[warp - 1];

    int run = base;
    for (int i = start; i < end; ++i) {
        int c = g_count[i];
        g_offset[i] = run;
        g_cursor[i] = run;
        run += c;
    }
}

// ---------------------------------------------------------------------------
// Kernel 4: scatter edges into CSR order (1 position-claim atomic per edge)
// ---------------------------------------------------------------------------
__global__ void edge_scatter_kernel(const int* __restrict__ edge_row,
                                    const int* __restrict__ edge_col,
                                    const float* __restrict__ edge_val,
                                    int E) {
    int e = blockIdx.x * blockDim.x + threadIdx.x;
    if (e >= E) return;
    int r = __ldg(edge_row + e);
    int pos = atomicAdd(&g_cursor[r], 1);
    g_edges[pos] = make_int2(__ldg(edge_col + e),
                             __float_as_int(__ldg(edge_val + e)));
}

// ---------------------------------------------------------------------------
// Kernel 5: fused gather-SpMM + dual hop (GEMM + bias + ReLU + norm) + sum.
//   Block = 64 nodes, 256 threads, static smem < 48KB:
//     sA[64][65]  : A tile, reused (x for hop0, agg for hop1)
//     sW[64*64]   : W^T, reused (W0 then W1)
//     sPar[6*64]  : b0,s0,o0,b1,s1,o1
//   Sequence: load x+W0 -> GEMM0+norm (stash regs) -> gather agg + load W1
//             -> GEMM1+norm -> out = r0 + r1.
//   GEMM mapping: t=0..255, f=t&7 (8 feats), g=t>>3 (2 nodes) -> acc[2][8].
// ---------------------------------------------------------------------------
#define STRIDE 65

__global__ __launch_bounds__(256)
void fused_kernel(const float* __restrict__ x,
                  const float* __restrict__ W0, const float* __restrict__ b0,
                  const float* __restrict__ s0, const float* __restrict__ o0,
                  const float* __restrict__ W1, const float* __restrict__ b1,
                  const float* __restrict__ s1, const float* __restrict__ o1,
                  float* __restrict__ out, int nNodes) {
    __shared__ float sA[64 * STRIDE];
    __shared__ float sW[D * D];
    __shared__ float sPar[6 * D];

    int tid = threadIdx.x;
    int nodeBase = blockIdx.x * 64;

    // ---- phase A: W0^T -> sW, params -> sPar, x tile -> sA ----
    for (int idx = tid; idx < D * D; idx += 256) {
        int j = idx >> 6, k = idx & 63;
        sW[k * 64 + j] = W0[idx];
    }
    for (int idx = tid; idx < 6 * D; idx += 256) {
        int which = idx >> 6, t = idx & 63;
        const float* src = (which == 0) ? b0 : (which == 1) ? s0 : (which == 2) ? o0
                         : (which == 3) ? b1 : (which == 4) ? s1 : o1;
        sPar[idx] = src[t];
    }
    {
        const float4* x4 = reinterpret_cast<const float4*>(x);
        for (int idx = tid; idx < 64 * 16; idx += 256) {
            int node = idx >> 4, q = idx & 15;
            int gnode = nodeBase + node;
            float4 v = make_float4(0.f, 0.f, 0.f, 0.f);
            if (gnode < nNodes) v = __ldg(&x4[gnode * 16 + q]);
            float* dst = sA + node * STRIDE + q * 4;
            dst[0] = v.x; dst[1] = v.y; dst[2] = v.z; dst[3] = v.w;
        }
    }
    __syncthreads();

    int f = tid & 7;     // feats f*8 .. f*8+7
    int g = tid >> 3;    // nodes g*2, g*2+1

    // ---- GEMM helper (macro-free inline): computes acc[2][8] from sA, sW ----
    float r0[2][8];      // hop0 normalized result stash
    {
        float acc[2][8];
        #pragma unroll
        for (int i = 0; i < 2; ++i)
            #pragma unroll
            for (int j = 0; j < 8; ++j) acc[i][j] = 0.f;

        const float* a0p = sA + (g * 2 + 0) * STRIDE;
        const float* a1p = sA + (g * 2 + 1) * STRIDE;
        #pragma unroll 8
        for (int k = 0; k < 64; ++k) {
            float a0 = a0p[k], a1 = a1p[k];
            const float* wr = sW + k * 64 + f * 8;
            float4 w0 = *reinterpret_cast<const float4*>(wr);
            float4 w1 = *reinterpret_cast<const float4*>(wr + 4);
            float w[8] = {w0.x, w0.y, w0.z, w0.w, w1.x, w1.y, w1.z, w1.w};
            #pragma unroll
            for (int j = 0; j < 8; ++j) {
                acc[0][j] = fmaf(a0, w[j], acc[0][j]);
                acc[1][j] = fmaf(a1, w[j], acc[1][j]);
            }
        }
        // epilogue hop0
        const float* bb = sPar;
        const float* sc = sPar + 64;
        const float* of = sPar + 128;
        #pragma unroll
        for (int i = 0; i < 2; ++i) {
            float s = 0.f, q = 0.f;
            #pragma unroll
            for (int j = 0; j < 8; ++j) {
                float h = fmaxf(acc[i][j] + bb[f * 8 + j], 0.f);
                acc[i][j] = h;
                s += h;
                q = fmaf(h, h, q);
            }
            #pragma unroll
            for (int off = 1; off < 8; off <<= 1) {
                s += __shfl_xor_sync(0xffffffffu, s, off);
                q += __shfl_xor_sync(0xffffffffu, q, off);
            }
            float mean = s * (1.0f / 64.0f);
            float var  = q * (1.0f / 64.0f) - mean * mean + EPS;
            float rinv = rsqrtf(var);
            #pragma unroll
            for (int j = 0; j < 8; ++j)
                r0[i][j] = (acc[i][j] - mean) * sc[f * 8 + j] * rinv + of[f * 8 + j];
        }
    }
    __syncthreads();   // GEMM0 reads of sA/sW done

    // ---- phase B: W1^T -> sW, gather agg -> sA ----
    for (int idx = tid; idx < D * D; idx += 256) {
        int j = idx >> 6, k = idx & 63;
        sW[k * 64 + j] = W1[idx];
    }
    {
        int node = tid >> 2, p = tid & 3;   // 4 threads/node, 16 feats each
        int gnode = nodeBase + node;
        float acc[16];
        #pragma unroll
        for (int i = 0; i < 16; ++i) acc[i] = 0.f;
        if (gnode < nNodes) {
            int start = g_offset[gnode];
            int cnt   = g_count[gnode];
            const float4* x4 = reinterpret_cast<const float4*>(x);
            #pragma unroll 2
            for (int e = 0; e < cnt; ++e) {
                int2 ev = __ldg(&g_edges[start + e]);
                float v = __int_as_float(ev.y);
                const float4* xr = x4 + (size_t)ev.x * 16 + p * 4;
                float4 v0 = __ldg(xr + 0);
                float4 v1 = __ldg(xr + 1);
                float4 v2 = __ldg(xr + 2);
                float4 v3 = __ldg(xr + 3);
                acc[0]  = fmaf(v, v0.x, acc[0]);  acc[1]  = fmaf(v, v0.y, acc[1]);
                acc[2]  = fmaf(v, v0.z, acc[2]);  acc[3]  = fmaf(v, v0.w, acc[3]);
                acc[4]  = fmaf(v, v1.x, acc[4]);  acc[5]  = fmaf(v, v1.y, acc[5]);
                acc[6]  = fmaf(v, v1.z, acc[6]);  acc[7]  = fmaf(v, v1.w, acc[7]);
                acc[8]  = fmaf(v, v2.x, acc[8]);  acc[9]  = fmaf(v, v2.y, acc[9]);
                acc[10] = fmaf(v, v2.z, acc[10]); acc[11] = fmaf(v, v2.w, acc[11]);
                acc[12] = fmaf(v, v3.x, acc[12]); acc[13] = fmaf(v, v3.y, acc[13]);
                acc[14] = fmaf(v, v3.z, acc[14]); acc[15] = fmaf(v, v3.w, acc[15]);
            }
        }
        float* dst = sA + node * STRIDE + p * 16;
        #pragma unroll
        for (int i = 0; i < 16; ++i) dst[i] = acc[i];
    }
    __syncthreads();

    // ---- GEMM hop1 + epilogue + combine + store ----
    {
        float acc[2][8];
        #pragma unroll
        for (int i = 0; i < 2; ++i)
            #pragma unroll
            for (int j = 0; j < 8; ++j) acc[i][j] = 0.f;

        const float* a0p = sA + (g * 2 + 0) * STRIDE;
        const float* a1p = sA + (g * 2 + 1) * STRIDE;
        #pragma unroll 8
        for (int k = 0; k < 64; ++k) {
            float a0 = a0p[k], a1 = a1p[k];
            const float* wr = sW + k * 64 + f * 8;
            float4 w0 = *reinterpret_cast<const float4*>(wr);
            float4 w1 = *reinterpret_cast<const float4*>(wr + 4);
            float w[8] = {w0.x, w0.y, w0.z, w0.w, w1.x, w1.y, w1.z, w1.w};
            #pragma unroll
            for (int j = 0; j < 8; ++j) {
                acc[0][j] = fmaf(a0, w[j], acc[0][j]);
                acc[1][j] = fmaf(a1, w[j], acc[1][j]);
            }
        }
        const float* bb = sPar + 192;
        const float* sc = sPar + 256;
        const float* of = sPar + 320;
        #pragma unroll
        for (int i = 0; i < 2; ++i) {
            float s = 0.f, q = 0.f;
            #pragma unroll
            for (int j = 0; j < 8; ++j) {
                float h = fmaxf(acc[i][j] + bb[f * 8 + j], 0.f);
                acc[i][j] = h;
                s += h;
                q = fmaf(h, h, q);
            }
            #pragma unroll
            for (int off = 1; off < 8; off <<= 1) {
                s += __shfl_xor_sync(0xffffffffu, s, off);
                q += __shfl_xor_sync(0xffffffffu, q, off);
            }
            float mean = s * (1.0f / 64.0f);
            float var  = q * (1.0f / 64.0f) - mean * mean + EPS;
            float rinv = rsqrtf(var);

            int gnode = nodeBase + g * 2 + i;
            if (gnode < nNodes) {
                float res[8];
                #pragma unroll
                for (int j = 0; j < 8; ++j) {
                    float r1 = (acc[i][j] - mean) * sc[f * 8 + j] * rinv + of[f * 8 + j];
                    res[j] = r0[i][j] + r1;
                }
                float4* dst = reinterpret_cast<float4*>(out + (size_t)gnode * D + f * 8);
                dst[0] = make_float4(res[0], res[1], res[2], res[3]);
                dst[1] = make_float4(res[4], res[5], res[6], res[7]);
            }
        }
    }
}

// ---------------------------------------------------------------------------
// Launch
// ---------------------------------------------------------------------------
extern "C" void kernel_launch(void* const* d_in, const int* in_sizes, int n_in,
                              void* d_out, int out_size) {
    const float* x        = (const float*)d_in[0];
    const float* edge_val = (const float*)d_in[1];
    const float* W0       = (const float*)d_in[2];
    const float* b0       = (const float*)d_in[3];
    const float* scale0   = (const float*)d_in[4];
    const float* offset0  = (const float*)d_in[5];
    const float* W1       = (const float*)d_in[6];
    const float* b1       = (const float*)d_in[7];
    const float* scale1   = (const float*)d_in[8];
    const float* offset1  = (const float*)d_in[9];
    const int*   edge_row = (const int*)d_in[10];
    const int*   edge_col = (const int*)d_in[11];
    float* out = (float*)d_out;

    int nNodes = in_sizes[0] / D;
    int E = in_sizes[1];

    zero_count_kernel<<<(nNodes + 255) / 256, 256>>>(nNodes);
    hist_kernel<<<(E + 255) / 256, 256>>>(edge_row, E);
    scan_kernel<<<1, 1024>>>(nNodes);
    edge_scatter_kernel<<<(E + 255) / 256, 256>>>(edge_row, edge_col, edge_val, E);

    int grid_c = (nNodes + 63) / 64;
    fused_kernel<<<grid_c, 256>>>(x, W0, b0, scale0, offset0,
                                  W1, b1, scale1, offset1, out, nNodes);
}

// round 7
// speedup vs baseline: 2.3035x; 2.1317x over previous
#include <cuda_runtime.h>
#include <cuda_bf16.h>

#define MAX_NODES 100000
#define MAX_EDGES 1600000
#define D 64
#define EPS 1e-9f

// Scratch (no allocations allowed -> device globals)
static __device__ int   g_count[MAX_NODES];
static __device__ int   g_offset[MAX_NODES];
static __device__ int   g_cursor[MAX_NODES];
static __device__ int2  g_edges[MAX_EDGES];     // (col, val-as-int) CSR-sorted
static __device__ float g_agg[MAX_NODES * D];   // aggregated features
static __device__ float g_WT0[D * D];           // W0^T  [k][j]
static __device__ float g_WT1[D * D];           // W1^T  [k][j]

// ---------------------------------------------------------------------------
// Kernel 0: transpose weights once (tiny)
// ---------------------------------------------------------------------------
__global__ void transpose_W_kernel(const float* __restrict__ W0,
                                   const float* __restrict__ W1) {
    for (int idx = blockIdx.x * blockDim.x + threadIdx.x; idx < D * D;
         idx += gridDim.x * blockDim.x) {
        int j = idx >> 6, k = idx & 63;
        g_WT0[k * 64 + j] = W0[idx];
        g_WT1[k * 64 + j] = W1[idx];
    }
}

// ---------------------------------------------------------------------------
// Kernel 1: zero histogram counters
// ---------------------------------------------------------------------------
__global__ void zero_count_kernel(int n) {
    int i = blockIdx.x * blockDim.x + threadIdx.x;
    if (i < n) g_count[i] = 0;
}

// ---------------------------------------------------------------------------
// Kernel 2: histogram of edge_row
// ---------------------------------------------------------------------------
__global__ void hist_kernel(const int* __restrict__ edge_row, int E) {
    int e = blockIdx.x * blockDim.x + threadIdx.x;
    if (e < E) atomicAdd(&g_count[__ldg(edge_row + e)], 1);
}

// ---------------------------------------------------------------------------
// Kernel 3: one-block exclusive scan over g_count -> g_offset, g_cursor
// ---------------------------------------------------------------------------
__global__ __launch_bounds__(1024)
void scan_kernel(int nNodes) {
    __shared__ int warpSums[32];
    int tid = threadIdx.x;
    const int chunk = 100;
    int start = tid * chunk;
    int end = start + chunk; if (end > nNodes) end = nNodes;

    int sum = 0;
    if (start < nNodes) {
        const int4* c4 = reinterpret_cast<const int4*>(g_count + start);
        int nfull = (end - start) >> 2;
        for (int i = 0; i < nfull; ++i) {
            int4 v = c4[i];
            sum += v.x + v.y + v.z + v.w;
        }
        for (int i = start + (nfull << 2); i < end; ++i) sum += g_count[i];
    }

    int lane = tid & 31, warp = tid >> 5;
    int v = sum;
    #pragma unroll
    for (int off = 1; off < 32; off <<= 1) {
        int t = __shfl_up_sync(0xffffffffu, v, off);
        if (lane >= off) v += t;
    }
    if (lane == 31) warpSums[warp] = v;
    __syncthreads();
    if (warp == 0) {
        int w = warpSums[lane];
        #pragma unroll
        for (int off = 1; off < 32; off <<= 1) {
            int t = __shfl_up_sync(0xffffffffu, w, off);
            if (lane >= off) w += t;
        }
        warpSums[lane] = w;
    }
    __syncthreads();
    int base = v - sum;
    if (warp > 0) base += warpSums[warp - 1];

    int run = base;
    for (int i = start; i < end; ++i) {
        int c = g_count[i];
        g_offset[i] = run;
        g_cursor[i] = run;
        run += c;
    }
}

// ---------------------------------------------------------------------------
// Kernel 4: scatter edges into CSR order
// ---------------------------------------------------------------------------
__global__ void edge_scatter_kernel(const int* __restrict__ edge_row,
                                    const int* __restrict__ edge_col,
                                    const float* __restrict__ edge_val,
                                    int E) {
    int e = blockIdx.x * blockDim.x + threadIdx.x;
    if (e >= E) return;
    int r = __ldg(edge_row + e);
    int pos = atomicAdd(&g_cursor[r], 1);
    g_edges[pos] = make_int2(__ldg(edge_col + e),
                             __float_as_int(__ldg(edge_val + e)));
}

// ---------------------------------------------------------------------------
// Kernel 5: gather-SpMM.  8 threads/node, 8 feats (32B) each.  No smem,
// low regs -> max occupancy to hide random L2 latency.  4-edge unroll.
// ---------------------------------------------------------------------------
__global__ __launch_bounds__(256)
void gather_kernel(const float* __restrict__ x, int nNodes) {
    int gid = blockIdx.x * 256 + threadIdx.x;
    int node = gid >> 3;
    int p = gid & 7;                 // feature octant: floats p*8 .. p*8+7
    if (node >= nNodes) return;

    int start = g_offset[node];
    int cnt   = g_count[node];
    const float4* x4 = reinterpret_cast<const float4*>(x);

    float4 acc0 = make_float4(0.f, 0.f, 0.f, 0.f);
    float4 acc1 = make_float4(0.f, 0.f, 0.f, 0.f);

    int e = 0;
    for (; e + 4 <= cnt; e += 4) {
        int2 e0 = __ldg(&g_edges[start + e + 0]);
        int2 e1 = __ldg(&g_edges[start + e + 1]);
        int2 e2 = __ldg(&g_edges[start + e + 2]);
        int2 e3 = __ldg(&g_edges[start + e + 3]);
        float4 a0 = __ldg(&x4[e0.x * 16 + p * 2]);
        float4 b0 = __ldg(&x4[e0.x * 16 + p * 2 + 1]);
        float4 a1 = __ldg(&x4[e1.x * 16 + p * 2]);
        float4 b1 = __ldg(&x4[e1.x * 16 + p * 2 + 1]);
        float4 a2 = __ldg(&x4[e2.x * 16 + p * 2]);
        float4 b2 = __ldg(&x4[e2.x * 16 + p * 2 + 1]);
        float4 a3 = __ldg(&x4[e3.x * 16 + p * 2]);
        float4 b3 = __ldg(&x4[e3.x * 16 + p * 2 + 1]);
        float v0 = __int_as_float(e0.y), v1 = __int_as_float(e1.y);
        float v2 = __int_as_float(e2.y), v3 = __int_as_float(e3.y);
        acc0.x = fmaf(v0, a0.x, acc0.x); acc0.y = fmaf(v0, a0.y, acc0.y);
        acc0.z = fmaf(v0, a0.z, acc0.z); acc0.w = fmaf(v0, a0.w, acc0.w);
        acc1.x = fmaf(v0, b0.x, acc1.x); acc1.y = fmaf(v0, b0.y, acc1.y);
        acc1.z = fmaf(v0, b0.z, acc1.z); acc1.w = fmaf(v0, b0.w, acc1.w);
        acc0.x = fmaf(v1, a1.x, acc0.x); acc0.y = fmaf(v1, a1.y, acc0.y);
        acc0.z = fmaf(v1, a1.z, acc0.z); acc0.w = fmaf(v1, a1.w, acc0.w);
        acc1.x = fmaf(v1, b1.x, acc1.x); acc1.y = fmaf(v1, b1.y, acc1.y);
        acc1.z = fmaf(v1, b1.z, acc1.z); acc1.w = fmaf(v1, b1.w, acc1.w);
        acc0.x = fmaf(v2, a2.x, acc0.x); acc0.y = fmaf(v2, a2.y, acc0.y);
        acc0.z = fmaf(v2, a2.z, acc0.z); acc0.w = fmaf(v2, a2.w, acc0.w);
        acc1.x = fmaf(v2, b2.x, acc1.x); acc1.y = fmaf(v2, b2.y, acc1.y);
        acc1.z = fmaf(v2, b2.z, acc1.z); acc1.w = fmaf(v2, b2.w, acc1.w);
        acc0.x = fmaf(v3, a3.x, acc0.x); acc0.y = fmaf(v3, a3.y, acc0.y);
        acc0.z = fmaf(v3, a3.z, acc0.z); acc0.w = fmaf(v3, a3.w, acc0.w);
        acc1.x = fmaf(v3, b3.x, acc1.x); acc1.y = fmaf(v3, b3.y, acc1.y);
        acc1.z = fmaf(v3, b3.z, acc1.z); acc1.w = fmaf(v3, b3.w, acc1.w);
    }
    for (; e < cnt; ++e) {
        int2 ev = __ldg(&g_edges[start + e]);
        float v = __int_as_float(ev.y);
        float4 a = __ldg(&x4[ev.x * 16 + p * 2]);
        float4 b = __ldg(&x4[ev.x * 16 + p * 2 + 1]);
        acc0.x = fmaf(v, a.x, acc0.x); acc0.y = fmaf(v, a.y, acc0.y);
        acc0.z = fmaf(v, a.z, acc0.z); acc0.w = fmaf(v, a.w, acc0.w);
        acc1.x = fmaf(v, b.x, acc1.x); acc1.y = fmaf(v, b.y, acc1.y);
        acc1.z = fmaf(v, b.z, acc1.z); acc1.w = fmaf(v, b.w, acc1.w);
    }

    float4* dst = reinterpret_cast<float4*>(g_agg + node * D + p * 8);
    dst[0] = acc0;
    dst[1] = acc1;
}

// ---------------------------------------------------------------------------
// Kernel 6: dual hop transform (GEMM + bias + ReLU + norm) + sum.
//   64 nodes/block, 256 threads.
//   Thread (f=t&7, g=t>>3): nodes g*2..g*2+1, feats {f*4..f*4+3, 32+f*4..+3}.
//   sA stride 68 (float4-aligned rows, conflict-free broadcasts);
//   sW stride 68: w float4 at k*68+f*4 -> banks 4(k+f)%32, conflict-free.
// ---------------------------------------------------------------------------
#define ASTRIDE 68

__global__ __launch_bounds__(256)
void transform_kernel(const float* __restrict__ x,
                      const float* __restrict__ b0, const float* __restrict__ s0,
                      const float* __restrict__ o0,
                      const float* __restrict__ b1, const float* __restrict__ s1,
                      const float* __restrict__ o1,
                      float* __restrict__ out, int nNodes) {
    __shared__ float sA[64 * ASTRIDE];
    __shared__ float sW[64 * ASTRIDE];
    __shared__ float sPar[6 * D];

    int tid = threadIdx.x;
    int nodeBase = blockIdx.x * 64;

    for (int idx = tid; idx < 6 * D; idx += 256) {
        int which = idx >> 6, t = idx & 63;
        const float* src = (which == 0) ? b0 : (which == 1) ? s0 : (which == 2) ? o0
                         : (which == 3) ? b1 : (which == 4) ? s1 : o1;
        sPar[idx] = src[t];
    }
    // W0^T -> sW (coalesced LDG.128 from g_WT0, float4 STS)
    {
        const float4* w4 = reinterpret_cast<const float4*>(g_WT0);
        for (int idx = tid; idx < 64 * 16; idx += 256) {
            int k = idx >> 4, c = idx & 15;
            *reinterpret_cast<float4*>(sW + k * ASTRIDE + c * 4) = __ldg(&w4[idx]);
        }
    }
    // x tile -> sA
    {
        const float4* x4 = reinterpret_cast<const float4*>(x);
        for (int idx = tid; idx < 64 * 16; idx += 256) {
            int node = idx >> 4, q = idx & 15;
            int gnode = nodeBase + node;
            float4 v = make_float4(0.f, 0.f, 0.f, 0.f);
            if (gnode < nNodes) v = __ldg(&x4[gnode * 16 + q]);
            *reinterpret_cast<float4*>(sA + node * ASTRIDE + q * 4) = v;
        }
    }
    __syncthreads();

    int f = tid & 7;
    int g = tid >> 3;
    int n0 = g * 2, n1 = g * 2 + 1;

    float r0[2][8];
    // ---------------- GEMM hop 0 ----------------
    {
        float acc[2][8];
        #pragma unroll
        for (int i = 0; i < 2; ++i)
            #pragma unroll
            for (int j = 0; j < 8; ++j) acc[i][j] = 0.f;

        #pragma unroll 4
        for (int k4 = 0; k4 < 16; ++k4) {
            float4 a0 = *reinterpret_cast<const float4*>(sA + n0 * ASTRIDE + k4 * 4);
            float4 a1 = *reinterpret_cast<const float4*>(sA + n1 * ASTRIDE + k4 * 4);
            float av0[4] = {a0.x, a0.y, a0.z, a0.w};
            float av1[4] = {a1.x, a1.y, a1.z, a1.w};
            #pragma unroll
            for (int kk = 0; kk < 4; ++kk) {
                int k = k4 * 4 + kk;
                float4 wl = *reinterpret_cast<const float4*>(sW + k * ASTRIDE + f * 4);
                float4 wh = *reinterpret_cast<const float4*>(sW + k * ASTRIDE + 32 + f * 4);
                float w[8] = {wl.x, wl.y, wl.z, wl.w, wh.x, wh.y, wh.z, wh.w};
                #pragma unroll
                for (int j = 0; j < 8; ++j) {
                    acc[0][j] = fmaf(av0[kk], w[j], acc[0][j]);
                    acc[1][j] = fmaf(av1[kk], w[j], acc[1][j]);
                }
            }
        }
        const float* bb = sPar;
        const float* sc = sPar + 64;
        const float* of = sPar + 128;
        #pragma unroll
        for (int i = 0; i < 2; ++i) {
            float s = 0.f, q = 0.f;
            #pragma unroll
            for (int j = 0; j < 8; ++j) {
                int feat = (j < 4) ? (f * 4 + j) : (32 + f * 4 + j - 4);
                float h = fmaxf(acc[i][j] + bb[feat], 0.f);
                acc[i][j] = h;
                s += h;
                q = fmaf(h, h, q);
            }
            #pragma unroll
            for (int off = 1; off < 8; off <<= 1) {
                s += __shfl_xor_sync(0xffffffffu, s, off);
                q += __shfl_xor_sync(0xffffffffu, q, off);
            }
            float mean = s * (1.0f / 64.0f);
            float var  = q * (1.0f / 64.0f) - mean * mean + EPS;
            float rinv = rsqrtf(var);
            #pragma unroll
            for (int j = 0; j < 8; ++j) {
                int feat = (j < 4) ? (f * 4 + j) : (32 + f * 4 + j - 4);
                r0[i][j] = (acc[i][j] - mean) * sc[feat] * rinv + of[feat];
            }
        }
    }
    __syncthreads();

    // ---------------- reload: W1^T, agg tile ----------------
    {
        const float4* w4 = reinterpret_cast<const float4*>(g_WT1);
        for (int idx = tid; idx < 64 * 16; idx += 256) {
            int k = idx >> 4, c = idx & 15;
            *reinterpret_cast<float4*>(sW + k * ASTRIDE + c * 4) = __ldg(&w4[idx]);
        }
        const float4* a4 = reinterpret_cast<const float4*>(g_agg);
        for (int idx = tid; idx < 64 * 16; idx += 256) {
            int node = idx >> 4, q = idx & 15;
            int gnode = nodeBase + node;
            float4 v = make_float4(0.f, 0.f, 0.f, 0.f);
            if (gnode < nNodes) v = a4[gnode * 16 + q];
            *reinterpret_cast<float4*>(sA + node * ASTRIDE + q * 4) = v;
        }
    }
    __syncthreads();

    // ---------------- GEMM hop 1 + combine + store ----------------
    {
        float acc[2][8];
        #pragma unroll
        for (int i = 0; i < 2; ++i)
            #pragma unroll
            for (int j = 0; j < 8; ++j) acc[i][j] = 0.f;

        #pragma unroll 4
        for (int k4 = 0; k4 < 16; ++k4) {
            float4 a0 = *reinterpret_cast<const float4*>(sA + n0 * ASTRIDE + k4 * 4);
            float4 a1 = *reinterpret_cast<const float4*>(sA + n1 * ASTRIDE + k4 * 4);
            float av0[4] = {a0.x, a0.y, a0.z, a0.w};
            float av1[4] = {a1.x, a1.y, a1.z, a1.w};
            #pragma unroll
            for (int kk = 0; kk < 4; ++kk) {
                int k = k4 * 4 + kk;
                float4 wl = *reinterpret_cast<const float4*>(sW + k * ASTRIDE + f * 4);
                float4 wh = *reinterpret_cast<const float4*>(sW + k * ASTRIDE + 32 + f * 4);
                float w[8] = {wl.x, wl.y, wl.z, wl.w, wh.x, wh.y, wh.z, wh.w};
                #pragma unroll
                for (int j = 0; j < 8; ++j) {
                    acc[0][j] = fmaf(av0[kk], w[j], acc[0][j]);
                    acc[1][j] = fmaf(av1[kk], w[j], acc[1][j]);
                }
            }
        }
        const float* bb = sPar + 192;
        const float* sc = sPar + 256;
        const float* of = sPar + 320;
        #pragma unroll
        for (int i = 0; i < 2; ++i) {
            float s = 0.f, q = 0.f;
            #pragma unroll
            for (int j = 0; j < 8; ++j) {
                int feat = (j < 4) ? (f * 4 + j) : (32 + f * 4 + j - 4);
                float h = fmaxf(acc[i][j] + bb[feat], 0.f);
                acc[i][j] = h;
                s += h;
                q = fmaf(h, h, q);
            }
            #pragma unroll
            for (int off = 1; off < 8; off <<= 1) {
                s += __shfl_xor_sync(0xffffffffu, s, off);
                q += __shfl_xor_sync(0xffffffffu, q, off);
            }
            float mean = s * (1.0f / 64.0f);
            float var  = q * (1.0f / 64.0f) - mean * mean + EPS;
            float rinv = rsqrtf(var);

            int gnode = nodeBase + g * 2 + i;
            if (gnode < nNodes) {
                float lo[4], hi[4];
                #pragma unroll
                for (int j = 0; j < 4; ++j) {
                    int feat = f * 4 + j;
                    lo[j] = r0[i][j] + (acc[i][j] - mean) * sc[feat] * rinv + of[feat];
                }
                #pragma unroll
                for (int j = 0; j < 4; ++j) {
                    int feat = 32 + f * 4 + j;
                    hi[j] = r0[i][4 + j] + (acc[i][4 + j] - mean) * sc[feat] * rinv + of[feat];
                }
                float* op = out + (size_t)gnode * D;
                *reinterpret_cast<float4*>(op + f * 4)      = make_float4(lo[0], lo[1], lo[2], lo[3]);
                *reinterpret_cast<float4*>(op + 32 + f * 4) = make_float4(hi[0], hi[1], hi[2], hi[3]);
            }
        }
    }
}

// ---------------------------------------------------------------------------
// Launch
// ---------------------------------------------------------------------------
extern "C" void kernel_launch(void* const* d_in, const int* in_sizes, int n_in,
                              void* d_out, int out_size) {
    const float* x        = (const float*)d_in[0];
    const float* edge_val = (const float*)d_in[1];
    const float* W0       = (const float*)d_in[2];
    const float* b0       = (const float*)d_in[3];
    const float* scale0   = (const float*)d_in[4];
    const float* offset0  = (const float*)d_in[5];
    const float* W1       = (const float*)d_in[6];
    const float* b1       = (const float*)d_in[7];
    const float* scale1   = (const float*)d_in[8];
    const float* offset1  = (const float*)d_in[9];
    const int*   edge_row = (const int*)d_in[10];
    const int*   edge_col = (const int*)d_in[11];
    float* out = (float*)d_out;

    int nNodes = in_sizes[0] / D;
    int E = in_sizes[1];

    transpose_W_kernel<<<16, 256>>>(W0, W1);
    zero_count_kernel<<<(nNodes + 255) / 256, 256>>>(nNodes);
    hist_kernel<<<(E + 255) / 256, 256>>>(edge_row, E);
    scan_kernel<<<1, 1024>>>(nNodes);
    edge_scatter_kernel<<<(E + 255) / 256, 256>>>(edge_row, edge_col, edge_val, E);

    int grid_g = (nNodes * 8 + 255) / 256;
    gather_kernel<<<grid_g, 256>>>(x, nNodes);

    int grid_t = (nNodes + 63) / 64;
    transform_kernel<<<grid_t, 256>>>(x, b0, scale0, offset0,
                                      b1, scale1, offset1, out, nNodes);
}

// round 8
// speedup vs baseline: 4.5963x; 1.9954x over previous
#include <cuda_runtime.h>
#include <cuda_bf16.h>

#define MAX_NODES 100000
#define MAX_EDGES 1600000
#define D 64
#define EPS 1e-9f

#define SCAN_TILE 1024          // nodes per scan block
#define MAX_SCAN_BLOCKS 128     // ceil(100000/1024)=98

// Scratch (no allocations allowed -> device globals)
static __device__ int   g_count[MAX_NODES];
static __device__ int   g_offset[MAX_NODES];
static __device__ int   g_cursor[MAX_NODES];
static __device__ int   g_blockSums[MAX_SCAN_BLOCKS];
static __device__ int2  g_edges[MAX_EDGES];     // (col, val-as-int) CSR-sorted
static __device__ float g_agg[MAX_NODES * D];   // aggregated features
static __device__ float g_WT0[D * D];           // W0^T  [k][j]
static __device__ float g_WT1[D * D];           // W1^T  [k][j]

// ---------------------------------------------------------------------------
// Kernel 0: transpose weights once (tiny)
// ---------------------------------------------------------------------------
__global__ void transpose_W_kernel(const float* __restrict__ W0,
                                   const float* __restrict__ W1) {
    for (int idx = blockIdx.x * blockDim.x + threadIdx.x; idx < D * D;
         idx += gridDim.x * blockDim.x) {
        int j = idx >> 6, k = idx & 63;
        g_WT0[k * 64 + j] = W0[idx];
        g_WT1[k * 64 + j] = W1[idx];
    }
}

// ---------------------------------------------------------------------------
// Kernel 1: zero histogram counters
// ---------------------------------------------------------------------------
__global__ void zero_count_kernel(int n) {
    int i = blockIdx.x * blockDim.x + threadIdx.x;
    if (i < n) g_count[i] = 0;
}

// ---------------------------------------------------------------------------
// Kernel 2: histogram of edge_row
// ---------------------------------------------------------------------------
__global__ void hist_kernel(const int* __restrict__ edge_row, int E) {
    int e = blockIdx.x * blockDim.x + threadIdx.x;
    if (e < E) atomicAdd(&g_count[__ldg(edge_row + e)], 1);
}

// ---------------------------------------------------------------------------
// Scan phase A: per-block sum of SCAN_TILE counts (256 thr, 4 nodes/thr)
// ---------------------------------------------------------------------------
__global__ __launch_bounds__(256)
void scan_reduce_kernel(int nNodes) {
    __shared__ int warpSums[8];
    int b = blockIdx.x;
    int base = b * SCAN_TILE + threadIdx.x * 4;

    int s = 0;
    if (base + 3 < nNodes) {
        int4 v = *reinterpret_cast<const int4*>(g_count + base);
        s = v.x + v.y + v.z + v.w;
    } else {
        for (int i = 0; i < 4; ++i)
            if (base + i < nNodes) s += g_count[base + i];
    }
    #pragma unroll
    for (int off = 16; off; off >>= 1)
        s += __shfl_xor_sync(0xffffffffu, s, off);
    int lane = threadIdx.x & 31, warp = threadIdx.x >> 5;
    if (lane == 0) warpSums[warp] = s;
    __syncthreads();
    if (threadIdx.x == 0) {
        int t = 0;
        #pragma unroll
        for (int w = 0; w < 8; ++w) t += warpSums[w];
        g_blockSums[b] = t;
    }
}

// ---------------------------------------------------------------------------
// Scan phase B: exclusive scan of block sums (single tiny block)
// ---------------------------------------------------------------------------
__global__ __launch_bounds__(128)
void scan_blocksums_kernel(int nBlocks) {
    __shared__ int warpTot[4];
    int tid = threadIdx.x;
    int v = (tid < nBlocks) ? g_blockSums[tid] : 0;
    int lane = tid & 31, warp = tid >> 5;
    int p = v;
    #pragma unroll
    for (int off = 1; off < 32; off <<= 1) {
        int t = __shfl_up_sync(0xffffffffu, p, off);
        if (lane >= off) p += t;
    }
    if (lane == 31) warpTot[warp] = p;
    __syncthreads();
    int add = 0;
    for (int w = 0; w < warp; ++w) add += warpTot[w];
    if (tid < nBlocks) g_blockSums[tid] = p - v + add;   // exclusive
}

// ---------------------------------------------------------------------------
// Scan phase C: per-block exclusive scan + write offsets/cursors
// ---------------------------------------------------------------------------
__global__ __launch_bounds__(256)
void scan_write_kernel(int nNodes) {
    __shared__ int warpSums[8];
    int b = blockIdx.x;
    int base = b * SCAN_TILE + threadIdx.x * 4;

    int c[4] = {0, 0, 0, 0};
    if (base + 3 < nNodes) {
        int4 v = *reinterpret_cast<const int4*>(g_count + base);
        c[0] = v.x; c[1] = v.y; c[2] = v.z; c[3] = v.w;
    } else {
        for (int i = 0; i < 4; ++i)
            if (base + i < nNodes) c[i] = g_count[base + i];
    }
    int local = c[0] + c[1] + c[2] + c[3];

    int lane = threadIdx.x & 31, warp = threadIdx.x >> 5;
    int p = local;
    #pragma unroll
    for (int off = 1; off < 32; off <<= 1) {
        int t = __shfl_up_sync(0xffffffffu, p, off);
        if (lane >= off) p += t;
    }
    if (lane == 31) warpSums[warp] = p;
    __syncthreads();
    int warpBase = 0;
    for (int w = 0; w < warp; ++w) warpBase += warpSums[w];
    int run = g_blockSums[b] + warpBase + (p - local);

    int o[4];
    o[0] = run;
    o[1] = o[0] + c[0];
    o[2] = o[1] + c[1];
    o[3] = o[2] + c[2];
    if (base + 3 < nNodes) {
        *reinterpret_cast<int4*>(g_offset + base) = make_int4(o[0], o[1], o[2], o[3]);
        *reinterpret_cast<int4*>(g_cursor + base) = make_int4(o[0], o[1], o[2], o[3]);
    } else {
        for (int i = 0; i < 4; ++i)
            if (base + i < nNodes) { g_offset[base + i] = o[i]; g_cursor[base + i] = o[i]; }
    }
}

// ---------------------------------------------------------------------------
// Kernel 4: scatter edges into CSR order
// ---------------------------------------------------------------------------
__global__ void edge_scatter_kernel(const int* __restrict__ edge_row,
                                    const int* __restrict__ edge_col,
                                    const float* __restrict__ edge_val,
                                    int E) {
    int e = blockIdx.x * blockDim.x + threadIdx.x;
    if (e >= E) return;
    int r = __ldg(edge_row + e);
    int pos = atomicAdd(&g_cursor[r], 1);
    g_edges[pos] = make_int2(__ldg(edge_col + e),
                             __float_as_int(__ldg(edge_val + e)));
}

// ---------------------------------------------------------------------------
// Kernel 5: gather-SpMM.  8 threads/node, 8 feats (32B) each.
// ---------------------------------------------------------------------------
__global__ __launch_bounds__(256)
void gather_kernel(const float* __restrict__ x, int nNodes) {
    int gid = blockIdx.x * 256 + threadIdx.x;
    int node = gid >> 3;
    int p = gid & 7;
    if (node >= nNodes) return;

    int start = g_offset[node];
    int cnt   = g_count[node];
    const float4* x4 = reinterpret_cast<const float4*>(x);

    float4 acc0 = make_float4(0.f, 0.f, 0.f, 0.f);
    float4 acc1 = make_float4(0.f, 0.f, 0.f, 0.f);

    int e = 0;
    for (; e + 4 <= cnt; e += 4) {
        int2 e0 = __ldg(&g_edges[start + e + 0]);
        int2 e1 = __ldg(&g_edges[start + e + 1]);
        int2 e2 = __ldg(&g_edges[start + e + 2]);
        int2 e3 = __ldg(&g_edges[start + e + 3]);
        float4 a0 = __ldg(&x4[e0.x * 16 + p * 2]);
        float4 b0 = __ldg(&x4[e0.x * 16 + p * 2 + 1]);
        float4 a1 = __ldg(&x4[e1.x * 16 + p * 2]);
        float4 b1 = __ldg(&x4[e1.x * 16 + p * 2 + 1]);
        float4 a2 = __ldg(&x4[e2.x * 16 + p * 2]);
        float4 b2 = __ldg(&x4[e2.x * 16 + p * 2 + 1]);
        float4 a3 = __ldg(&x4[e3.x * 16 + p * 2]);
        float4 b3 = __ldg(&x4[e3.x * 16 + p * 2 + 1]);
        float v0 = __int_as_float(e0.y), v1 = __int_as_float(e1.y);
        float v2 = __int_as_float(e2.y), v3 = __int_as_float(e3.y);
        acc0.x = fmaf(v0, a0.x, acc0.x); acc0.y = fmaf(v0, a0.y, acc0.y);
        acc0.z = fmaf(v0, a0.z, acc0.z); acc0.w = fmaf(v0, a0.w, acc0.w);
        acc1.x = fmaf(v0, b0.x, acc1.x); acc1.y = fmaf(v0, b0.y, acc1.y);
        acc1.z = fmaf(v0, b0.z, acc1.z); acc1.w = fmaf(v0, b0.w, acc1.w);
        acc0.x = fmaf(v1, a1.x, acc0.x); acc0.y = fmaf(v1, a1.y, acc0.y);
        acc0.z = fmaf(v1, a1.z, acc0.z); acc0.w = fmaf(v1, a1.w, acc0.w);
        acc1.x = fmaf(v1, b1.x, acc1.x); acc1.y = fmaf(v1, b1.y, acc1.y);
        acc1.z = fmaf(v1, b1.z, acc1.z); acc1.w = fmaf(v1, b1.w, acc1.w);
        acc0.x = fmaf(v2, a2.x, acc0.x); acc0.y = fmaf(v2, a2.y, acc0.y);
        acc0.z = fmaf(v2, a2.z, acc0.z); acc0.w = fmaf(v2, a2.w, acc0.w);
        acc1.x = fmaf(v2, b2.x, acc1.x); acc1.y = fmaf(v2, b2.y, acc1.y);
        acc1.z = fmaf(v2, b2.z, acc1.z); acc1.w = fmaf(v2, b2.w, acc1.w);
        acc0.x = fmaf(v3, a3.x, acc0.x); acc0.y = fmaf(v3, a3.y, acc0.y);
        acc0.z = fmaf(v3, a3.z, acc0.z); acc0.w = fmaf(v3, a3.w, acc0.w);
        acc1.x = fmaf(v3, b3.x, acc1.x); acc1.y = fmaf(v3, b3.y, acc1.y);
        acc1.z = fmaf(v3, b3.z, acc1.z); acc1.w = fmaf(v3, b3.w, acc1.w);
    }
    for (; e < cnt; ++e) {
        int2 ev = __ldg(&g_edges[start + e]);
        float v = __int_as_float(ev.y);
        float4 a = __ldg(&x4[ev.x * 16 + p * 2]);
        float4 b = __ldg(&x4[ev.x * 16 + p * 2 + 1]);
        acc0.x = fmaf(v, a.x, acc0.x); acc0.y = fmaf(v, a.y, acc0.y);
        acc0.z = fmaf(v, a.z, acc0.z); acc0.w = fmaf(v, a.w, acc0.w);
        acc1.x = fmaf(v, b.x, acc1.x); acc1.y = fmaf(v, b.y, acc1.y);
        acc1.z = fmaf(v, b.z, acc1.z); acc1.w = fmaf(v, b.w, acc1.w);
    }

    float4* dst = reinterpret_cast<float4*>(g_agg + node * D + p * 8);
    dst[0] = acc0;
    dst[1] = acc1;
}

// ---------------------------------------------------------------------------
// Kernel 6: dual hop transform (GEMM + bias + ReLU + norm) + sum.
// ---------------------------------------------------------------------------
#define ASTRIDE 68

__global__ __launch_bounds__(256)
void transform_kernel(const float* __restrict__ x,
                      const float* __restrict__ b0, const float* __restrict__ s0,
                      const float* __restrict__ o0,
                      const float* __restrict__ b1, const float* __restrict__ s1,
                      const float* __restrict__ o1,
                      float* __restrict__ out, int nNodes) {
    __shared__ float sA[64 * ASTRIDE];
    __shared__ float sW[64 * ASTRIDE];
    __shared__ float sPar[6 * D];

    int tid = threadIdx.x;
    int nodeBase = blockIdx.x * 64;

    for (int idx = tid; idx < 6 * D; idx += 256) {
        int which = idx >> 6, t = idx & 63;
        const float* src = (which == 0) ? b0 : (which == 1) ? s0 : (which == 2) ? o0
                         : (which == 3) ? b1 : (which == 4) ? s1 : o1;
        sPar[idx] = src[t];
    }
    {
        const float4* w4 = reinterpret_cast<const float4*>(g_WT0);
        for (int idx = tid; idx < 64 * 16; idx += 256) {
            int k = idx >> 4, c = idx & 15;
            *reinterpret_cast<float4*>(sW + k * ASTRIDE + c * 4) = __ldg(&w4[idx]);
        }
    }
    {
        const float4* x4 = reinterpret_cast<const float4*>(x);
        for (int idx = tid; idx < 64 * 16; idx += 256) {
            int node = idx >> 4, q = idx & 15;
            int gnode = nodeBase + node;
            float4 v = make_float4(0.f, 0.f, 0.f, 0.f);
            if (gnode < nNodes) v = __ldg(&x4[gnode * 16 + q]);
            *reinterpret_cast<float4*>(sA + node * ASTRIDE + q * 4) = v;
        }
    }
    __syncthreads();

    int f = tid & 7;
    int g = tid >> 3;
    int n0 = g * 2, n1 = g * 2 + 1;

    float r0[2][8];
    // ---------------- GEMM hop 0 ----------------
    {
        float acc[2][8];
        #pragma unroll
        for (int i = 0; i < 2; ++i)
            #pragma unroll
            for (int j = 0; j < 8; ++j) acc[i][j] = 0.f;

        #pragma unroll 4
        for (int k4 = 0; k4 < 16; ++k4) {
            float4 a0 = *reinterpret_cast<const float4*>(sA + n0 * ASTRIDE + k4 * 4);
            float4 a1 = *reinterpret_cast<const float4*>(sA + n1 * ASTRIDE + k4 * 4);
            float av0[4] = {a0.x, a0.y, a0.z, a0.w};
            float av1[4] = {a1.x, a1.y, a1.z, a1.w};
            #pragma unroll
            for (int kk = 0; kk < 4; ++kk) {
                int k = k4 * 4 + kk;
                float4 wl = *reinterpret_cast<const float4*>(sW + k * ASTRIDE + f * 4);
                float4 wh = *reinterpret_cast<const float4*>(sW + k * ASTRIDE + 32 + f * 4);
                float w[8] = {wl.x, wl.y, wl.z, wl.w, wh.x, wh.y, wh.z, wh.w};
                #pragma unroll
                for (int j = 0; j < 8; ++j) {
                    acc[0][j] = fmaf(av0[kk], w[j], acc[0][j]);
                    acc[1][j] = fmaf(av1[kk], w[j], acc[1][j]);
                }
            }
        }
        const float* bb = sPar;
        const float* sc = sPar + 64;
        const float* of = sPar + 128;
        #pragma unroll
        for (int i = 0; i < 2; ++i) {
            float s = 0.f, q = 0.f;
            #pragma unroll
            for (int j = 0; j < 8; ++j) {
                int feat = (j < 4) ? (f * 4 + j) : (32 + f * 4 + j - 4);
                float h = fmaxf(acc[i][j] + bb[feat], 0.f);
                acc[i][j] = h;
                s += h;
                q = fmaf(h, h, q);
            }
            #pragma unroll
            for (int off = 1; off < 8; off <<= 1) {
                s += __shfl_xor_sync(0xffffffffu, s, off);
                q += __shfl_xor_sync(0xffffffffu, q, off);
            }
            float mean = s * (1.0f / 64.0f);
            float var  = q * (1.0f / 64.0f) - mean * mean + EPS;
            float rinv = rsqrtf(var);
            #pragma unroll
            for (int j = 0; j < 8; ++j) {
                int feat = (j < 4) ? (f * 4 + j) : (32 + f * 4 + j - 4);
                r0[i][j] = (acc[i][j] - mean) * sc[feat] * rinv + of[feat];
            }
        }
    }
    __syncthreads();

    // ---------------- reload: W1^T, agg tile ----------------
    {
        const float4* w4 = reinterpret_cast<const float4*>(g_WT1);
        for (int idx = tid; idx < 64 * 16; idx += 256) {
            int k = idx >> 4, c = idx & 15;
            *reinterpret_cast<float4*>(sW + k * ASTRIDE + c * 4) = __ldg(&w4[idx]);
        }
        const float4* a4 = reinterpret_cast<const float4*>(g_agg);
        for (int idx = tid; idx < 64 * 16; idx += 256) {
            int node = idx >> 4, q = idx & 15;
            int gnode = nodeBase + node;
            float4 v = make_float4(0.f, 0.f, 0.f, 0.f);
            if (gnode < nNodes) v = a4[gnode * 16 + q];
            *reinterpret_cast<float4*>(sA + node * ASTRIDE + q * 4) = v;
        }
    }
    __syncthreads();

    // ---------------- GEMM hop 1 + combine + store ----------------
    {
        float acc[2][8];
        #pragma unroll
        for (int i = 0; i < 2; ++i)
            #pragma unroll
            for (int j = 0; j < 8; ++j) acc[i][j] = 0.f;

        #pragma unroll 4
        for (int k4 = 0; k4 < 16; ++k4) {
            float4 a0 = *reinterpret_cast<const float4*>(sA + n0 * ASTRIDE + k4 * 4);
            float4 a1 = *reinterpret_cast<const float4*>(sA + n1 * ASTRIDE + k4 * 4);
            float av0[4] = {a0.x, a0.y, a0.z, a0.w};
            float av1[4] = {a1.x, a1.y, a1.z, a1.w};
            #pragma unroll
            for (int kk = 0; kk < 4; ++kk) {
                int k = k4 * 4 + kk;
                float4 wl = *reinterpret_cast<const float4*>(sW + k * ASTRIDE + f * 4);
                float4 wh = *reinterpret_cast<const float4*>(sW + k * ASTRIDE + 32 + f * 4);
                float w[8] = {wl.x, wl.y, wl.z, wl.w, wh.x, wh.y, wh.z, wh.w};
                #pragma unroll
                for (int j = 0; j < 8; ++j) {
                    acc[0][j] = fmaf(av0[kk], w[j], acc[0][j]);
                    acc[1][j] = fmaf(av1[kk], w[j], acc[1][j]);
                }
            }
        }
        const float* bb = sPar + 192;
        const float* sc = sPar + 256;
        const float* of = sPar + 320;
        #pragma unroll
        for (int i = 0; i < 2; ++i) {
            float s = 0.f, q = 0.f;
            #pragma unroll
            for (int j = 0; j < 8; ++j) {
                int feat = (j < 4) ? (f * 4 + j) : (32 + f * 4 + j - 4);
                float h = fmaxf(acc[i][j] + bb[feat], 0.f);
                acc[i][j] = h;
                s += h;
                q = fmaf(h, h, q);
            }
            #pragma unroll
            for (int off = 1; off < 8; off <<= 1) {
                s += __shfl_xor_sync(0xffffffffu, s, off);
                q += __shfl_xor_sync(0xffffffffu, q, off);
            }
            float mean = s * (1.0f / 64.0f);
            float var  = q * (1.0f / 64.0f) - mean * mean + EPS;
            float rinv = rsqrtf(var);

            int gnode = nodeBase + g * 2 + i;
            if (gnode < nNodes) {
                float lo[4], hi[4];
                #pragma unroll
                for (int j = 0; j < 4; ++j) {
                    int feat = f * 4 + j;
                    lo[j] = r0[i][j] + (acc[i][j] - mean) * sc[feat] * rinv + of[feat];
                }
                #pragma unroll
                for (int j = 0; j < 4; ++j) {
                    int feat = 32 + f * 4 + j;
                    hi[j] = r0[i][4 + j] + (acc[i][4 + j] - mean) * sc[feat] * rinv + of[feat];
                }
                float* op = out + (size_t)gnode * D;
                *reinterpret_cast<float4*>(op + f * 4)      = make_float4(lo[0], lo[1], lo[2], lo[3]);
                *reinterpret_cast<float4*>(op + 32 + f * 4) = make_float4(hi[0], hi[1], hi[2], hi[3]);
            }
        }
    }
}

// ---------------------------------------------------------------------------
// Launch
// ---------------------------------------------------------------------------
extern "C" void kernel_launch(void* const* d_in, const int* in_sizes, int n_in,
                              void* d_out, int out_size) {
    const float* x        = (const float*)d_in[0];
    const float* edge_val = (const float*)d_in[1];
    const float* W0       = (const float*)d_in[2];
    const float* b0       = (const float*)d_in[3];
    const float* scale0   = (const float*)d_in[4];
    const float* offset0  = (const float*)d_in[5];
    const float* W1       = (const float*)d_in[6];
    const float* b1       = (const float*)d_in[7];
    const float* scale1   = (const float*)d_in[8];
    const float* offset1  = (const float*)d_in[9];
    const int*   edge_row = (const int*)d_in[10];
    const int*   edge_col = (const int*)d_in[11];
    float* out = (float*)d_out;

    int nNodes = in_sizes[0] / D;
    int E = in_sizes[1];

    transpose_W_kernel<<<16, 256>>>(W0, W1);
    zero_count_kernel<<<(nNodes + 255) / 256, 256>>>(nNodes);
    hist_kernel<<<(E + 255) / 256, 256>>>(edge_row, E);

    int nScanBlocks = (nNodes + SCAN_TILE - 1) / SCAN_TILE;
    scan_reduce_kernel<<<nScanBlocks, 256>>>(nNodes);
    scan_blocksums_kernel<<<1, 128>>>(nScanBlocks);
    scan_write_kernel<<<nScanBlocks, 256>>>(nNodes);

    edge_scatter_kernel<<<(E + 255) / 256, 256>>>(edge_row, edge_col, edge_val, E);

    int grid_g = (nNodes * 8 + 255) / 256;
    gather_kernel<<<grid_g, 256>>>(x, nNodes);

    int grid_t = (nNodes + 63) / 64;
    transform_kernel<<<grid_t, 256>>>(x, b0, scale0, offset0,
                                      b1, scale1, offset1, out, nNodes);
}

// round 10
// speedup vs baseline: 4.8030x; 1.0450x over previous
#include <cuda_runtime.h>

#define MAX_NODES 100000
#define MAX_EDGES 1600000
#define D 64
#define EPS 1e-9f

#define SCAN_TILE 1024
#define MAX_SCAN_BLOCKS 128

// Scratch (no allocations allowed -> device globals)
static __device__ int   g_count[MAX_NODES];
static __device__ int   g_offset[MAX_NODES];
static __device__ int   g_rank[MAX_EDGES];      // per-edge rank within its row
static __device__ int   g_blockSums[MAX_SCAN_BLOCKS];
static __device__ int2  g_edges[MAX_EDGES];     // (col, val-as-int) CSR-sorted
static __device__ float g_agg[MAX_NODES * D];   // aggregated features
static __device__ float g_WT0[D * D];           // W0^T  [k][j]
static __device__ float g_WT1[D * D];           // W1^T  [k][j]

// ---------------------------------------------------------------------------
// Kernel 0: transpose weights + zero counters (merged)
// ---------------------------------------------------------------------------
__global__ void prep_kernel(const float* __restrict__ W0,
                            const float* __restrict__ W1, int nNodes) {
    int gid = blockIdx.x * blockDim.x + threadIdx.x;
    if (gid < D * D) {
        int j = gid >> 6, k = gid & 63;
        g_WT0[k * 64 + j] = W0[gid];
        g_WT1[k * 64 + j] = W1[gid];
    }
    for (int i = gid; i < nNodes; i += gridDim.x * blockDim.x)
        g_count[i] = 0;
}

// ---------------------------------------------------------------------------
// Kernel 1: histogram of edge_row; atomic returns the edge's rank
// ---------------------------------------------------------------------------
__global__ void hist_kernel(const int* __restrict__ edge_row, int E) {
    int e = blockIdx.x * blockDim.x + threadIdx.x;
    if (e < E) g_rank[e] = atomicAdd(&g_count[__ldg(edge_row + e)], 1);
}

// ---------------------------------------------------------------------------
// Scan phase A: per-block sum of SCAN_TILE counts
// ---------------------------------------------------------------------------
__global__ __launch_bounds__(256)
void scan_reduce_kernel(int nNodes) {
    __shared__ int warpSums[8];
    int b = blockIdx.x;
    int base = b * SCAN_TILE + threadIdx.x * 4;

    int s = 0;
    if (base + 3 < nNodes) {
        int4 v = *reinterpret_cast<const int4*>(g_count + base);
        s = v.x + v.y + v.z + v.w;
    } else {
        for (int i = 0; i < 4; ++i)
            if (base + i < nNodes) s += g_count[base + i];
    }
    #pragma unroll
    for (int off = 16; off; off >>= 1)
        s += __shfl_xor_sync(0xffffffffu, s, off);
    int lane = threadIdx.x & 31, warp = threadIdx.x >> 5;
    if (lane == 0) warpSums[warp] = s;
    __syncthreads();
    if (threadIdx.x == 0) {
        int t = 0;
        #pragma unroll
        for (int w = 0; w < 8; ++w) t += warpSums[w];
        g_blockSums[b] = t;
    }
}

// ---------------------------------------------------------------------------
// Scan phase B: exclusive scan of block sums
// ---------------------------------------------------------------------------
__global__ __launch_bounds__(128)
void scan_blocksums_kernel(int nBlocks) {
    __shared__ int warpTot[4];
    int tid = threadIdx.x;
    int v = (tid < nBlocks) ? g_blockSums[tid] : 0;
    int lane = tid & 31, warp = tid >> 5;
    int p = v;
    #pragma unroll
    for (int off = 1; off < 32; off <<= 1) {
        int t = __shfl_up_sync(0xffffffffu, p, off);
        if (lane >= off) p += t;
    }
    if (lane == 31) warpTot[warp] = p;
    __syncthreads();
    int add = 0;
    for (int w = 0; w < warp; ++w) add += warpTot[w];
    if (tid < nBlocks) g_blockSums[tid] = p - v + add;
}

// ---------------------------------------------------------------------------
// Scan phase C: per-block exclusive scan + write offsets
// ---------------------------------------------------------------------------
__global__ __launch_bounds__(256)
void scan_write_kernel(int nNodes) {
    __shared__ int warpSums[8];
    int b = blockIdx.x;
    int base = b * SCAN_TILE + threadIdx.x * 4;

    int c[4] = {0, 0, 0, 0};
    if (base + 3 < nNodes) {
        int4 v = *reinterpret_cast<const int4*>(g_count + base);
        c[0] = v.x; c[1] = v.y; c[2] = v.z; c[3] = v.w;
    } else {
        for (int i = 0; i < 4; ++i)
            if (base + i < nNodes) c[i] = g_count[base + i];
    }
    int local = c[0] + c[1] + c[2] + c[3];

    int lane = threadIdx.x & 31, warp = threadIdx.x >> 5;
    int p = local;
    #pragma unroll
    for (int off = 1; off < 32; off <<= 1) {
        int t = __shfl_up_sync(0xffffffffu, p, off);
        if (lane >= off) p += t;
    }
    if (lane == 31) warpSums[warp] = p;
    __syncthreads();
    int warpBase = 0;
    for (int w = 0; w < warp; ++w) warpBase += warpSums[w];
    int run = g_blockSums[b] + warpBase + (p - local);

    int o[4];
    o[0] = run;
    o[1] = o[0] + c[0];
    o[2] = o[1] + c[1];
    o[3] = o[2] + c[2];
    if (base + 3 < nNodes) {
        *reinterpret_cast<int4*>(g_offset + base) = make_int4(o[0], o[1], o[2], o[3]);
    } else {
        for (int i = 0; i < 4; ++i)
            if (base + i < nNodes) g_offset[base + i] = o[i];
    }
}

// ---------------------------------------------------------------------------
// Kernel 4: scatter edges into CSR order — atomic-free (uses g_rank)
// ---------------------------------------------------------------------------
__global__ void edge_scatter_kernel(const int* __restrict__ edge_row,
                                    const int* __restrict__ edge_col,
                                    const float* __restrict__ edge_val,
                                    int E) {
    int e = blockIdx.x * blockDim.x + threadIdx.x;
    if (e >= E) return;
    int r = __ldg(edge_row + e);
    int pos = __ldg(&g_offset[r]) + g_rank[e];
    g_edges[pos] = make_int2(__ldg(edge_col + e),
                             __float_as_int(__ldg(edge_val + e)));
}

// ---------------------------------------------------------------------------
// Kernel 5: gather-SpMM.  8 threads/node, 8 feats (32B) each.
// ---------------------------------------------------------------------------
__global__ __launch_bounds__(256)
void gather_kernel(const float* __restrict__ x, int nNodes) {
    int gid = blockIdx.x * 256 + threadIdx.x;
    int node = gid >> 3;
    int p = gid & 7;
    if (node >= nNodes) return;

    int start = g_offset[node];
    int cnt   = g_count[node];
    const float4* x4 = reinterpret_cast<const float4*>(x);

    float4 acc0 = make_float4(0.f, 0.f, 0.f, 0.f);
    float4 acc1 = make_float4(0.f, 0.f, 0.f, 0.f);

    int e = 0;
    for (; e + 4 <= cnt; e += 4) {
        int2 e0 = __ldg(&g_edges[start + e + 0]);
        int2 e1 = __ldg(&g_edges[start + e + 1]);
        int2 e2 = __ldg(&g_edges[start + e + 2]);
        int2 e3 = __ldg(&g_edges[start + e + 3]);
        float4 a0 = __ldg(&x4[e0.x * 16 + p * 2]);
        float4 b0 = __ldg(&x4[e0.x * 16 + p * 2 + 1]);
        float4 a1 = __ldg(&x4[e1.x * 16 + p * 2]);
        float4 b1 = __ldg(&x4[e1.x * 16 + p * 2 + 1]);
        float4 a2 = __ldg(&x4[e2.x * 16 + p * 2]);
        float4 b2 = __ldg(&x4[e2.x * 16 + p * 2 + 1]);
        float4 a3 = __ldg(&x4[e3.x * 16 + p * 2]);
        float4 b3 = __ldg(&x4[e3.x * 16 + p * 2 + 1]);
        float v0 = __int_as_float(e0.y), v1 = __int_as_float(e1.y);
        float v2 = __int_as_float(e2.y), v3 = __int_as_float(e3.y);
        acc0.x = fmaf(v0, a0.x, acc0.x); acc0.y = fmaf(v0, a0.y, acc0.y);
        acc0.z = fmaf(v0, a0.z, acc0.z); acc0.w = fmaf(v0, a0.w, acc0.w);
        acc1.x = fmaf(v0, b0.x, acc1.x); acc1.y = fmaf(v0, b0.y, acc1.y);
        acc1.z = fmaf(v0, b0.z, acc1.z); acc1.w = fmaf(v0, b0.w, acc1.w);
        acc0.x = fmaf(v1, a1.x, acc0.x); acc0.y = fmaf(v1, a1.y, acc0.y);
        acc0.z = fmaf(v1, a1.z, acc0.z); acc0.w = fmaf(v1, a1.w, acc0.w);
        acc1.x = fmaf(v1, b1.x, acc1.x); acc1.y = fmaf(v1, b1.y, acc1.y);
        acc1.z = fmaf(v1, b1.z, acc1.z); acc1.w = fmaf(v1, b1.w, acc1.w);
        acc0.x = fmaf(v2, a2.x, acc0.x); acc0.y = fmaf(v2, a2.y, acc0.y);
        acc0.z = fmaf(v2, a2.z, acc0.z); acc0.w = fmaf(v2, a2.w, acc0.w);
        acc1.x = fmaf(v2, b2.x, acc1.x); acc1.y = fmaf(v2, b2.y, acc1.y);
        acc1.z = fmaf(v2, b2.z, acc1.z); acc1.w = fmaf(v2, b2.w, acc1.w);
        acc0.x = fmaf(v3, a3.x, acc0.x); acc0.y = fmaf(v3, a3.y, acc0.y);
        acc0.z = fmaf(v3, a3.z, acc0.z); acc0.w = fmaf(v3, a3.w, acc0.w);
        acc1.x = fmaf(v3, b3.x, acc1.x); acc1.y = fmaf(v3, b3.y, acc1.y);
        acc1.z = fmaf(v3, b3.z, acc1.z); acc1.w = fmaf(v3, b3.w, acc1.w);
    }
    for (; e < cnt; ++e) {
        int2 ev = __ldg(&g_edges[start + e]);
        float v = __int_as_float(ev.y);
        float4 a = __ldg(&x4[ev.x * 16 + p * 2]);
        float4 b = __ldg(&x4[ev.x * 16 + p * 2 + 1]);
        acc0.x = fmaf(v, a.x, acc0.x); acc0.y = fmaf(v, a.y, acc0.y);
        acc0.z = fmaf(v, a.z, acc0.z); acc0.w = fmaf(v, a.w, acc0.w);
        acc1.x = fmaf(v, b.x, acc1.x); acc1.y = fmaf(v, b.y, acc1.y);
        acc1.z = fmaf(v, b.z, acc1.z); acc1.w = fmaf(v, b.w, acc1.w);
    }

    float4* dst = reinterpret_cast<float4*>(g_agg + node * D + p * 8);
    dst[0] = acc0;
    dst[1] = acc1;
}

// ---------------------------------------------------------------------------
// Kernel 6: dual hop transform.  128 threads, 64 nodes/block.
//   Thread (f=t&7, g=t>>3): nodes g*4..g*4+3, feats {f*4..+3, 32+f*4..+3}.
// ---------------------------------------------------------------------------
#define ASTRIDE 68

__global__ __launch_bounds__(128)
void transform_kernel(const float* __restrict__ x,
                      const float* __restrict__ b0, const float* __restrict__ s0,
                      const float* __restrict__ o0,
                      const float* __restrict__ b1, const float* __restrict__ s1,
                      const float* __restrict__ o1,
                      float* __restrict__ out, int nNodes) {
    __shared__ float sA[64 * ASTRIDE];
    __shared__ float sW[64 * ASTRIDE];
    __shared__ float sPar[6 * D];

    int tid = threadIdx.x;
    int nodeBase = blockIdx.x * 64;

    for (int idx = tid; idx < 6 * D; idx += 128) {
        int which = idx >> 6, t = idx & 63;
        const float* src = (which == 0) ? b0 : (which == 1) ? s0 : (which == 2) ? o0
                         : (which == 3) ? b1 : (which == 4) ? s1 : o1;
        sPar[idx] = src[t];
    }
    {
        const float4* w4 = reinterpret_cast<const float4*>(g_WT0);
        for (int idx = tid; idx < 64 * 16; idx += 128) {
            int k = idx >> 4, c = idx & 15;
            *reinterpret_cast<float4*>(sW + k * ASTRIDE + c * 4) = __ldg(&w4[idx]);
        }
        const float4* x4 = reinterpret_cast<const float4*>(x);
        for (int idx = tid; idx < 64 * 16; idx += 128) {
            int node = idx >> 4, q = idx & 15;
            int gnode = nodeBase + node;
            float4 v = make_float4(0.f, 0.f, 0.f, 0.f);
            if (gnode < nNodes) v = __ldg(&x4[gnode * 16 + q]);
            *reinterpret_cast<float4*>(sA + node * ASTRIDE + q * 4) = v;
        }
    }
    __syncthreads();

    int f = tid & 7;
    int g = tid >> 3;          // 0..15, nodes g*4 .. g*4+3

    float r0[4][8];
    // ---------------- GEMM hop 0 ----------------
    {
        float acc[4][8];
        #pragma unroll
        for (int i = 0; i < 4; ++i)
            #pragma unroll
            for (int j = 0; j < 8; ++j) acc[i][j] = 0.f;

        #pragma unroll 2
        for (int k4 = 0; k4 < 16; ++k4) {
            float4 av[4];
            #pragma unroll
            for (int i = 0; i < 4; ++i)
                av[i] = *reinterpret_cast<const float4*>(sA + (g * 4 + i) * ASTRIDE + k4 * 4);
            #pragma unroll
            for (int kk = 0; kk < 4; ++kk) {
                int k = k4 * 4 + kk;
                float4 wl = *reinterpret_cast<const float4*>(sW + k * ASTRIDE + f * 4);
                float4 wh = *reinterpret_cast<const float4*>(sW + k * ASTRIDE + 32 + f * 4);
                float w[8] = {wl.x, wl.y, wl.z, wl.w, wh.x, wh.y, wh.z, wh.w};
                #pragma unroll
                for (int i = 0; i < 4; ++i) {
                    float a = (kk == 0) ? av[i].x : (kk == 1) ? av[i].y
                            : (kk == 2) ? av[i].z : av[i].w;
                    #pragma unroll
                    for (int j = 0; j < 8; ++j)
                        acc[i][j] = fmaf(a, w[j], acc[i][j]);
                }
            }
        }
        const float* bb = sPar;
        const float* sc = sPar + 64;
        const float* of = sPar + 128;
        #pragma unroll
        for (int i = 0; i < 4; ++i) {
            float s = 0.f, q = 0.f;
            #pragma unroll
            for (int j = 0; j < 8; ++j) {
                int feat = (j < 4) ? (f * 4 + j) : (32 + f * 4 + j - 4);
                float h = fmaxf(acc[i][j] + bb[feat], 0.f);
                acc[i][j] = h;
                s += h;
                q = fmaf(h, h, q);
            }
            #pragma unroll
            for (int off = 1; off < 8; off <<= 1) {
                s += __shfl_xor_sync(0xffffffffu, s, off);
                q += __shfl_xor_sync(0xffffffffu, q, off);
            }
            float mean = s * (1.0f / 64.0f);
            float var  = q * (1.0f / 64.0f) - mean * mean + EPS;
            float rinv = rsqrtf(var);
            #pragma unroll
            for (int j = 0; j < 8; ++j) {
                int feat = (j < 4) ? (f * 4 + j) : (32 + f * 4 + j - 4);
                r0[i][j] = (acc[i][j] - mean) * sc[feat] * rinv + of[feat];
            }
        }
    }
    __syncthreads();

    // ---------------- reload: W1^T, agg tile ----------------
    {
        const float4* w4 = reinterpret_cast<const float4*>(g_WT1);
        for (int idx = tid; idx < 64 * 16; idx += 128) {
            int k = idx >> 4, c = idx & 15;
            *reinterpret_cast<float4*>(sW + k * ASTRIDE + c * 4) = __ldg(&w4[idx]);
        }
        const float4* a4 = reinterpret_cast<const float4*>(g_agg);
        for (int idx = tid; idx < 64 * 16; idx += 128) {
            int node = idx >> 4, q = idx & 15;
            int gnode = nodeBase + node;
            float4 v = make_float4(0.f, 0.f, 0.f, 0.f);
            if (gnode < nNodes) v = a4[gnode * 16 + q];
            *reinterpret_cast<float4*>(sA + node * ASTRIDE + q * 4) = v;
        }
    }
    __syncthreads();

    // ---------------- GEMM hop 1 + combine + store ----------------
    {
        float acc[4][8];
        #pragma unroll
        for (int i = 0; i < 4; ++i)
            #pragma unroll
            for (int j = 0; j < 8; ++j) acc[i][j] = 0.f;

        #pragma unroll 2
        for (int k4 = 0; k4 < 16; ++k4) {
            float4 av[4];
            #pragma unroll
            for (int i = 0; i < 4; ++i)
                av[i] = *reinterpret_cast<const float4*>(sA + (g * 4 + i) * ASTRIDE + k4 * 4);
            #pragma unroll
            for (int kk = 0; kk < 4; ++kk) {
                int k = k4 * 4 + kk;
                float4 wl = *reinterpret_cast<const float4*>(sW + k * ASTRIDE + f * 4);
                float4 wh = *reinterpret_cast<const float4*>(sW + k * ASTRIDE + 32 + f * 4);
                float w[8] = {wl.x, wl.y, wl.z, wl.w, wh.x, wh.y, wh.z, wh.w};
                #pragma unroll
                for (int i = 0; i < 4; ++i) {
                    float a = (kk == 0) ? av[i].x : (kk == 1) ? av[i].y
                            : (kk == 2) ? av[i].z : av[i].w;
                    #pragma unroll
                    for (int j = 0; j < 8; ++j)
                        acc[i][j] = fmaf(a, w[j], acc[i][j]);
                }
            }
        }
        const float* bb = sPar + 192;
        const float* sc = sPar + 256;
        const float* of = sPar + 320;
        #pragma unroll
        for (int i = 0; i < 4; ++i) {
            float s = 0.f, q = 0.f;
            #pragma unroll
            for (int j = 0; j < 8; ++j) {
                int feat = (j < 4) ? (f * 4 + j) : (32 + f * 4 + j - 4);
                float h = fmaxf(acc[i][j] + bb[feat], 0.f);
                acc[i][j] = h;
                s += h;
                q = fmaf(h, h, q);
            }
            #pragma unroll
            for (int off = 1; off < 8; off <<= 1) {
                s += __shfl_xor_sync(0xffffffffu, s, off);
                q += __shfl_xor_sync(0xffffffffu, q, off);
            }
            float mean = s * (1.0f / 64.0f);
            float var  = q * (1.0f / 64.0f) - mean * mean + EPS;
            float rinv = rsqrtf(var);

            int gnode = nodeBase + g * 4 + i;
            if (gnode < nNodes) {
                float lo[4], hi[4];
                #pragma unroll
                for (int j = 0; j < 4; ++j) {
                    int feat = f * 4 + j;
                    lo[j] = r0[i][j] + (acc[i][j] - mean) * sc[feat] * rinv + of[feat];
                }
                #pragma unroll
                for (int j = 0; j < 4; ++j) {
                    int feat = 32 + f * 4 + j;
                    hi[j] = r0[i][4 + j] + (acc[i][4 + j] - mean) * sc[feat] * rinv + of[feat];
                }
                float* op = out + (size_t)gnode * D;
                *reinterpret_cast<float4*>(op + f * 4)      = make_float4(lo[0], lo[1], lo[2], lo[3]);
                *reinterpret_cast<float4*>(op + 32 + f * 4) = make_float4(hi[0], hi[1], hi[2], hi[3]);
            }
        }
    }
}

// ---------------------------------------------------------------------------
// Launch
// ---------------------------------------------------------------------------
extern "C" void kernel_launch(void* const* d_in, const int* in_sizes, int n_in,
                              void* d_out, int out_size) {
    const float* x        = (const float*)d_in[0];
    const float* edge_val = (const float*)d_in[1];
    const float* W0       = (const float*)d_in[2];
    const float* b0       = (const float*)d_in[3];
    const float* scale0   = (const float*)d_in[4];
    const float* offset0  = (const float*)d_in[5];
    const float* W1       = (const float*)d_in[6];
    const float* b1       = (const float*)d_in[7];
    const float* scale1   = (const float*)d_in[8];
    const float* offset1  = (const float*)d_in[9];
    const int*   edge_row = (const int*)d_in[10];
    const int*   edge_col = (const int*)d_in[11];
    float* out = (float*)d_out;

    int nNodes = in_sizes[0] / D;
    int E = in_sizes[1];

    prep_kernel<<<64, 256>>>(W0, W1, nNodes);
    hist_kernel<<<(E + 255) / 256, 256>>>(edge_row, E);

    int nScanBlocks = (nNodes + SCAN_TILE - 1) / SCAN_TILE;
    scan_reduce_kernel<<<nScanBlocks, 256>>>(nNodes);
    scan_blocksums_kernel<<<1, 128>>>(nScanBlocks);
    scan_write_kernel<<<nScanBlocks, 256>>>(nNodes);

    edge_scatter_kernel<<<(E + 255) / 256, 256>>>(edge_row, edge_col, edge_val, E);

    int grid_g = (nNodes * 8 + 255) / 256;
    gather_kernel<<<grid_g, 256>>>(x, nNodes);

    int grid_t = (nNodes + 63) / 64;
    transform_kernel<<<grid_t, 128>>>(x, b0, scale0, offset0,
                                      b1, scale1, offset1, out, nNodes);
}

// round 12
// speedup vs baseline: 5.0617x; 1.0539x over previous
#include <cuda_runtime.h>

#define MAX_NODES 100000
#define MAX_EDGES 1600000
#define D 64
#define EPS 1e-9f

#define SCAN_TILE 1024
#define MAX_SCAN_BLOCKS 128

// Scratch (no allocations allowed -> device globals)
static __device__ int   g_count[MAX_NODES];
static __device__ int   g_offset[MAX_NODES];
static __device__ int   g_rank[MAX_EDGES];      // per-edge rank within its row
static __device__ int   g_blockSums[MAX_SCAN_BLOCKS];
static __device__ int2  g_edges[MAX_EDGES];     // (col, val-as-int) CSR-sorted
static __device__ float g_agg[MAX_NODES * D];   // aggregated features
static __device__ float g_WT0[D * D];           // W0^T  [k][j]
static __device__ float g_WT1[D * D];           // W1^T  [k][j]

// ---- packed f32x2 helpers (sm_100+) ----
__device__ __forceinline__ unsigned long long fma2(unsigned long long a,
                                                   unsigned long long b,
                                                   unsigned long long c) {
    unsigned long long d;
    asm("fma.rn.f32x2 %0, %1, %2, %3;" : "=l"(d) : "l"(a), "l"(b), "l"(c));
    return d;
}
__device__ __forceinline__ unsigned long long pack2(float a) {
    unsigned long long r;
    asm("mov.b64 %0, {%1, %1};" : "=l"(r) : "f"(a));
    return r;
}
__device__ __forceinline__ void unpack2(unsigned long long v, float& lo, float& hi) {
    asm("mov.b64 {%0, %1}, %2;" : "=f"(lo), "=f"(hi) : "l"(v));
}

// ---------------------------------------------------------------------------
// Kernel 0: transpose weights + zero counters (merged)
// ---------------------------------------------------------------------------
__global__ void prep_kernel(const float* __restrict__ W0,
                            const float* __restrict__ W1, int nNodes) {
    int gid = blockIdx.x * blockDim.x + threadIdx.x;
    if (gid < D * D) {
        int j = gid >> 6, k = gid & 63;
        g_WT0[k * 64 + j] = W0[gid];
        g_WT1[k * 64 + j] = W1[gid];
    }
    for (int i = gid; i < nNodes; i += gridDim.x * blockDim.x)
        g_count[i] = 0;
}

// ---------------------------------------------------------------------------
// Kernel 1: histogram of edge_row; atomic returns the edge's rank
// ---------------------------------------------------------------------------
__global__ void hist_kernel(const int* __restrict__ edge_row, int E) {
    int e = blockIdx.x * blockDim.x + threadIdx.x;
    if (e < E) g_rank[e] = atomicAdd(&g_count[__ldg(edge_row + e)], 1);
}

// ---------------------------------------------------------------------------
// Scan phase A: per-block sum of SCAN_TILE counts
// ---------------------------------------------------------------------------
__global__ __launch_bounds__(256)
void scan_reduce_kernel(int nNodes) {
    __shared__ int warpSums[8];
    int b = blockIdx.x;
    int base = b * SCAN_TILE + threadIdx.x * 4;

    int s = 0;
    if (base + 3 < nNodes) {
        int4 v = *reinterpret_cast<const int4*>(g_count + base);
        s = v.x + v.y + v.z + v.w;
    } else {
        for (int i = 0; i < 4; ++i)
            if (base + i < nNodes) s += g_count[base + i];
    }
    #pragma unroll
    for (int off = 16; off; off >>= 1)
        s += __shfl_xor_sync(0xffffffffu, s, off);
    int lane = threadIdx.x & 31, warp = threadIdx.x >> 5;
    if (lane == 0) warpSums[warp] = s;
    __syncthreads();
    if (threadIdx.x == 0) {
        int t = 0;
        #pragma unroll
        for (int w = 0; w < 8; ++w) t += warpSums[w];
        g_blockSums[b] = t;
    }
}

// ---------------------------------------------------------------------------
// Scan phase B: exclusive scan of block sums
// ---------------------------------------------------------------------------
__global__ __launch_bounds__(128)
void scan_blocksums_kernel(int nBlocks) {
    __shared__ int warpTot[4];
    int tid = threadIdx.x;
    int v = (tid < nBlocks) ? g_blockSums[tid] : 0;
    int lane = tid & 31, warp = tid >> 5;
    int p = v;
    #pragma unroll
    for (int off = 1; off < 32; off <<= 1) {
        int t = __shfl_up_sync(0xffffffffu, p, off);
        if (lane >= off) p += t;
    }
    if (lane == 31) warpTot[warp] = p;
    __syncthreads();
    int add = 0;
    for (int w = 0; w < warp; ++w) add += warpTot[w];
    if (tid < nBlocks) g_blockSums[tid] = p - v + add;
}

// ---------------------------------------------------------------------------
// Scan phase C: per-block exclusive scan + write offsets
// ---------------------------------------------------------------------------
__global__ __launch_bounds__(256)
void scan_write_kernel(int nNodes) {
    __shared__ int warpSums[8];
    int b = blockIdx.x;
    int base = b * SCAN_TILE + threadIdx.x * 4;

    int c[4] = {0, 0, 0, 0};
    if (base + 3 < nNodes) {
        int4 v = *reinterpret_cast<const int4*>(g_count + base);
        c[0] = v.x; c[1] = v.y; c[2] = v.z; c[3] = v.w;
    } else {
        for (int i = 0; i < 4; ++i)
            if (base + i < nNodes) c[i] = g_count[base + i];
    }
    int local = c[0] + c[1] + c[2] + c[3];

    int lane = threadIdx.x & 31, warp = threadIdx.x >> 5;
    int p = local;
    #pragma unroll
    for (int off = 1; off < 32; off <<= 1) {
        int t = __shfl_up_sync(0xffffffffu, p, off);
        if (lane >= off) p += t;
    }
    if (lane == 31) warpSums[warp] = p;
    __syncthreads();
    int warpBase = 0;
    for (int w = 0; w < warp; ++w) warpBase += warpSums[w];
    int run = g_blockSums[b] + warpBase + (p - local);

    int o[4];
    o[0] = run;
    o[1] = o[0] + c[0];
    o[2] = o[1] + c[1];
    o[3] = o[2] + c[2];
    if (base + 3 < nNodes) {
        *reinterpret_cast<int4*>(g_offset + base) = make_int4(o[0], o[1], o[2], o[3]);
    } else {
        for (int i = 0; i < 4; ++i)
            if (base + i < nNodes) g_offset[base + i] = o[i];
    }
}

// ---------------------------------------------------------------------------
// Kernel 4: scatter edges into CSR order — atomic-free (uses g_rank)
// ---------------------------------------------------------------------------
__global__ void edge_scatter_kernel(const int* __restrict__ edge_row,
                                    const int* __restrict__ edge_col,
                                    const float* __restrict__ edge_val,
                                    int E) {
    int e = blockIdx.x * blockDim.x + threadIdx.x;
    if (e >= E) return;
    int r = __ldg(edge_row + e);
    int pos = __ldg(&g_offset[r]) + g_rank[e];
    g_edges[pos] = make_int2(__ldg(edge_col + e),
                             __float_as_int(__ldg(edge_val + e)));
}

// ---------------------------------------------------------------------------
// Kernel 5: gather-SpMM.  8 threads/node (one warp octet), 8 feats each.
//   Edge list read ONCE per octet (lane p loads edge base+p), broadcast via
//   shfl width-8. Octets of a warp may diverge (different cnt) -> group mask.
// ---------------------------------------------------------------------------
__global__ __launch_bounds__(256)
void gather_kernel(const float* __restrict__ x, int nNodes) {
    int gid = blockIdx.x * 256 + threadIdx.x;
    int node = gid >> 3;
    int p = gid & 7;
    if (node >= nNodes) return;

    int lane = threadIdx.x & 31;
    unsigned gmask = 0xFFu << (lane & 24);

    int start = g_offset[node];
    int cnt   = g_count[node];
    const float4* x4 = reinterpret_cast<const float4*>(x);

    float4 acc0 = make_float4(0.f, 0.f, 0.f, 0.f);
    float4 acc1 = make_float4(0.f, 0.f, 0.f, 0.f);

    for (int base = 0; base < cnt; base += 8) {
        int idx = base + p;
        int2 ev = (idx < cnt) ? __ldg(&g_edges[start + idx]) : make_int2(0, 0);
        int m = cnt - base; if (m > 8) m = 8;
        #pragma unroll 4
        for (int t = 0; t < m; ++t) {
            int   col = __shfl_sync(gmask, ev.x, t, 8);
            float v   = __int_as_float(__shfl_sync(gmask, ev.y, t, 8));
            float4 a = __ldg(&x4[col * 16 + p * 2]);
            float4 b = __ldg(&x4[col * 16 + p * 2 + 1]);
            acc0.x = fmaf(v, a.x, acc0.x); acc0.y = fmaf(v, a.y, acc0.y);
            acc0.z = fmaf(v, a.z, acc0.z); acc0.w = fmaf(v, a.w, acc0.w);
            acc1.x = fmaf(v, b.x, acc1.x); acc1.y = fmaf(v, b.y, acc1.y);
            acc1.z = fmaf(v, b.z, acc1.z); acc1.w = fmaf(v, b.w, acc1.w);
        }
    }

    float4* dst = reinterpret_cast<float4*>(g_agg + node * D + p * 8);
    dst[0] = acc0;
    dst[1] = acc1;
}

// ---------------------------------------------------------------------------
// Kernel 6: dual hop transform with packed f32x2 FMA.
//   128 threads, 64 nodes/block. Thread (f=t&7, g=t>>3): nodes g*4..g*4+3,
//   feats {f*4..+3, 32+f*4..+3} as 4 packed pairs.
// ---------------------------------------------------------------------------
#define ASTRIDE 68

__global__ __launch_bounds__(128)
void transform_kernel(const float* __restrict__ x,
                      const float* __restrict__ b0, const float* __restrict__ s0,
                      const float* __restrict__ o0,
                      const float* __restrict__ b1, const float* __restrict__ s1,
                      const float* __restrict__ o1,
                      float* __restrict__ out, int nNodes) {
    __shared__ float sA[64 * ASTRIDE];
    __shared__ float sW[64 * ASTRIDE];
    __shared__ float sPar[6 * D];

    int tid = threadIdx.x;
    int nodeBase = blockIdx.x * 64;

    for (int idx = tid; idx < 6 * D; idx += 128) {
        int which = idx >> 6, t = idx & 63;
        const float* src = (which == 0) ? b0 : (which == 1) ? s0 : (which == 2) ? o0
                         : (which == 3) ? b1 : (which == 4) ? s1 : o1;
        sPar[idx] = src[t];
    }
    {
        const float4* w4 = reinterpret_cast<const float4*>(g_WT0);
        for (int idx = tid; idx < 64 * 16; idx += 128) {
            int k = idx >> 4, c = idx & 15;
            *reinterpret_cast<float4*>(sW + k * ASTRIDE + c * 4) = __ldg(&w4[idx]);
        }
        const float4* x4 = reinterpret_cast<const float4*>(x);
        for (int idx = tid; idx < 64 * 16; idx += 128) {
            int node = idx >> 4, q = idx & 15;
            int gnode = nodeBase + node;
            float4 v = make_float4(0.f, 0.f, 0.f, 0.f);
            if (gnode < nNodes) v = __ldg(&x4[gnode * 16 + q]);
            *reinterpret_cast<float4*>(sA + node * ASTRIDE + q * 4) = v;
        }
    }
    __syncthreads();

    int f = tid & 7;
    int g = tid >> 3;          // 0..15, nodes g*4 .. g*4+3

    float r0[4][8];
    // ---------------- GEMM hop 0 (f32x2) ----------------
    {
        unsigned long long acc2[4][4];
        #pragma unroll
        for (int i = 0; i < 4; ++i)
            #pragma unroll
            for (int j = 0; j < 4; ++j) acc2[i][j] = 0ull;

        #pragma unroll 2
        for (int k4 = 0; k4 < 16; ++k4) {
            float4 av[4];
            #pragma unroll
            for (int i = 0; i < 4; ++i)
                av[i] = *reinterpret_cast<const float4*>(sA + (g * 4 + i) * ASTRIDE + k4 * 4);
            #pragma unroll
            for (int kk = 0; kk < 4; ++kk) {
                int k = k4 * 4 + kk;
                ulonglong2 wl = *reinterpret_cast<const ulonglong2*>(sW + k * ASTRIDE + f * 4);
                ulonglong2 wh = *reinterpret_cast<const ulonglong2*>(sW + k * ASTRIDE + 32 + f * 4);
                #pragma unroll
                for (int i = 0; i < 4; ++i) {
                    float a = (kk == 0) ? av[i].x : (kk == 1) ? av[i].y
                            : (kk == 2) ? av[i].z : av[i].w;
                    unsigned long long pa = pack2(a);
                    acc2[i][0] = fma2(pa, wl.x, acc2[i][0]);
                    acc2[i][1] = fma2(pa, wl.y, acc2[i][1]);
                    acc2[i][2] = fma2(pa, wh.x, acc2[i][2]);
                    acc2[i][3] = fma2(pa, wh.y, acc2[i][3]);
                }
            }
        }
        const float* bb = sPar;
        const float* sc = sPar + 64;
        const float* of = sPar + 128;
        #pragma unroll
        for (int i = 0; i < 4; ++i) {
            float acc[8];
            unpack2(acc2[i][0], acc[0], acc[1]);
            unpack2(acc2[i][1], acc[2], acc[3]);
            unpack2(acc2[i][2], acc[4], acc[5]);
            unpack2(acc2[i][3], acc[6], acc[7]);
            float s = 0.f, q = 0.f;
            #pragma unroll
            for (int j = 0; j < 8; ++j) {
                int feat = (j < 4) ? (f * 4 + j) : (32 + f * 4 + j - 4);
                float h = fmaxf(acc[j] + bb[feat], 0.f);
                acc[j] = h;
                s += h;
                q = fmaf(h, h, q);
            }
            #pragma unroll
            for (int off = 1; off < 8; off <<= 1) {
                s += __shfl_xor_sync(0xffffffffu, s, off);
                q += __shfl_xor_sync(0xffffffffu, q, off);
            }
            float mean = s * (1.0f / 64.0f);
            float var  = q * (1.0f / 64.0f) - mean * mean + EPS;
            float rinv = rsqrtf(var);
            #pragma unroll
            for (int j = 0; j < 8; ++j) {
                int feat = (j < 4) ? (f * 4 + j) : (32 + f * 4 + j - 4);
                r0[i][j] = (acc[j] - mean) * sc[feat] * rinv + of[feat];
            }
        }
    }
    __syncthreads();

    // ---------------- reload: W1^T, agg tile ----------------
    {
        const float4* w4 = reinterpret_cast<const float4*>(g_WT1);
        for (int idx = tid; idx < 64 * 16; idx += 128) {
            int k = idx >> 4, c = idx & 15;
            *reinterpret_cast<float4*>(sW + k * ASTRIDE + c * 4) = __ldg(&w4[idx]);
        }
        const float4* a4 = reinterpret_cast<const float4*>(g_agg);
        for (int idx = tid; idx < 64 * 16; idx += 128) {
            int node = idx >> 4, q = idx & 15;
            int gnode = nodeBase + node;
            float4 v = make_float4(0.f, 0.f, 0.f, 0.f);
            if (gnode < nNodes) v = a4[gnode * 16 + q];
            *reinterpret_cast<float4*>(sA + node * ASTRIDE + q * 4) = v;
        }
    }
    __syncthreads();

    // ---------------- GEMM hop 1 (f32x2) + combine + store ----------------
    {
        unsigned long long acc2[4][4];
        #pragma unroll
        for (int i = 0; i < 4; ++i)
            #pragma unroll
            for (int j = 0; j < 4; ++j) acc2[i][j] = 0ull;

        #pragma unroll 2
        for (int k4 = 0; k4 < 16; ++k4) {
            float4 av[4];
            #pragma unroll
            for (int i = 0; i < 4; ++i)
                av[i] = *reinterpret_cast<const float4*>(sA + (g * 4 + i) * ASTRIDE + k4 * 4);
            #pragma unroll
            for (int kk = 0; kk < 4; ++kk) {
                int k = k4 * 4 + kk;
                ulonglong2 wl = *reinterpret_cast<const ulonglong2*>(sW + k * ASTRIDE + f * 4);
                ulonglong2 wh = *reinterpret_cast<const ulonglong2*>(sW + k * ASTRIDE + 32 + f * 4);
                #pragma unroll
                for (int i = 0; i < 4; ++i) {
                    float a = (kk == 0) ? av[i].x : (kk == 1) ? av[i].y
                            : (kk == 2) ? av[i].z : av[i].w;
                    unsigned long long pa = pack2(a);
                    acc2[i][0] = fma2(pa, wl.x, acc2[i][0]);
                    acc2[i][1] = fma2(pa, wl.y, acc2[i][1]);
                    acc2[i][2] = fma2(pa, wh.x, acc2[i][2]);
                    acc2[i][3] = fma2(pa, wh.y, acc2[i][3]);
                }
            }
        }
        const float* bb = sPar + 192;
        const float* sc = sPar + 256;
        const float* of = sPar + 320;
        #pragma unroll
        for (int i = 0; i < 4; ++i) {
            float acc[8];
            unpack2(acc2[i][0], acc[0], acc[1]);
            unpack2(acc2[i][1], acc[2], acc[3]);
            unpack2(acc2[i][2], acc[4], acc[5]);
            unpack2(acc2[i][3], acc[6], acc[7]);
            float s = 0.f, q = 0.f;
            #pragma unroll
            for (int j = 0; j < 8; ++j) {
                int feat = (j < 4) ? (f * 4 + j) : (32 + f * 4 + j - 4);
                float h = fmaxf(acc[j] + bb[feat], 0.f);
                acc[j] = h;
                s += h;
                q = fmaf(h, h, q);
            }
            #pragma unroll
            for (int off = 1; off < 8; off <<= 1) {
                s += __shfl_xor_sync(0xffffffffu, s, off);
                q += __shfl_xor_sync(0xffffffffu, q, off);
            }
            float mean = s * (1.0f / 64.0f);
            float var  = q * (1.0f / 64.0f) - mean * mean + EPS;
            float rinv = rsqrtf(var);

            int gnode = nodeBase + g * 4 + i;
            if (gnode < nNodes) {
                float lo[4], hi[4];
                #pragma unroll
                for (int j = 0; j < 4; ++j) {
                    int feat = f * 4 + j;
                    lo[j] = r0[i][j] + (acc[j] - mean) * sc[feat] * rinv + of[feat];
                }
                #pragma unroll
                for (int j = 0; j < 4; ++j) {
                    int feat = 32 + f * 4 + j;
                    hi[j] = r0[i][4 + j] + (acc[4 + j] - mean) * sc[feat] * rinv + of[feat];
                }
                float* op = out + (size_t)gnode * D;
                *reinterpret_cast<float4*>(op + f * 4)      = make_float4(lo[0], lo[1], lo[2], lo[3]);
                *reinterpret_cast<float4*>(op + 32 + f * 4) = make_float4(hi[0], hi[1], hi[2], hi[3]);
            }
        }
    }
}

// ---------------------------------------------------------------------------
// Launch
// ---------------------------------------------------------------------------
extern "C" void kernel_launch(void* const* d_in, const int* in_sizes, int n_in,
                              void* d_out, int out_size) {
    const float* x        = (const float*)d_in[0];
    const float* edge_val = (const float*)d_in[1];
    const float* W0       = (const float*)d_in[2];
    const float* b0       = (const float*)d_in[3];
    const float* scale0   = (const float*)d_in[4];
    const float* offset0  = (const float*)d_in[5];
    const float* W1       = (const float*)d_in[6];
    const float* b1       = (const float*)d_in[7];
    const float* scale1   = (const float*)d_in[8];
    const float* offset1  = (const float*)d_in[9];
    const int*   edge_row = (const int*)d_in[10];
    const int*   edge_col = (const int*)d_in[11];
    float* out = (float*)d_out;

    int nNodes = in_sizes[0] / D;
    int E = in_sizes[1];

    prep_kernel<<<64, 256>>>(W0, W1, nNodes);
    hist_kernel<<<(E + 255) / 256, 256>>>(edge_row, E);

    int nScanBlocks = (nNodes + SCAN_TILE - 1) / SCAN_TILE;
    scan_reduce_kernel<<<nScanBlocks, 256>>>(nNodes);
    scan_blocksums_kernel<<<1, 128>>>(nScanBlocks);
    scan_write_kernel<<<nScanBlocks, 256>>>(nNodes);

    edge_scatter_kernel<<<(E + 255) / 256, 256>>>(edge_row, edge_col, edge_val, E);

    int grid_g = (nNodes * 8 + 255) / 256;
    gather_kernel<<<grid_g, 256>>>(x, nNodes);

    int grid_t = (nNodes + 63) / 64;
    transform_kernel<<<grid_t, 128>>>(x, b0, scale0, offset0,
                                      b1, scale1, offset1, out, nNodes);
}